// round 2
// baseline (speedup 1.0000x reference)
#include <cuda_runtime.h>

#define BATCH 2
#define SEQ   2048
#define DM    1024
#define NH    16
#define DK    64

// ---------------- scratch (allocation-free: device globals) ----------------
__device__ float g_xn[BATCH * SEQ * DM];          // normalized x
__device__ float g_q[BATCH * SEQ * DM];
__device__ float g_k[BATCH * SEQ * DM];
__device__ float g_v[BATCH * SEQ * DM];
__device__ unsigned char g_mask[BATCH * SEQ * SEQ]; // 1 byte per (b,s,t)

// ---------------- 1) row normalization ----------------
__global__ __launch_bounds__(256) void norm_kernel(const float* __restrict__ x) {
    int row = blockIdx.x;                 // 0..B*S-1
    int t = threadIdx.x;
    const float4* xr = (const float4*)(x + (size_t)row * DM);
    float4* xo = (float4*)(g_xn + (size_t)row * DM);
    float4 v = xr[t];                     // 256 threads * 4 = 1024
    float ss = v.x * v.x + v.y * v.y + v.z * v.z + v.w * v.w;
    __shared__ float red[8];
#pragma unroll
    for (int o = 16; o; o >>= 1) ss += __shfl_xor_sync(~0u, ss, o);
    if ((t & 31) == 0) red[t >> 5] = ss;
    __syncthreads();
    if (t < 8) {
        float s = red[t];
#pragma unroll
        for (int o = 4; o; o >>= 1) s += __shfl_xor_sync(0xffu, s, o);
        if (t == 0) red[0] = s;
    }
    __syncthreads();
    float inv = 1.0f / fmaxf(sqrtf(red[0]), 1e-12f);
    v.x *= inv; v.y *= inv; v.z *= inv; v.w *= inv;
    xo[t] = v;
}

// ---------------- shared GEMM tile: C[128x128] = A(Mx1024) * B(Nx1024)^T ----
// A, B already offset to block row starts. K fixed = 1024, both K-contiguous.
__device__ __forceinline__ void gemm128_nt(const float* __restrict__ A,
                                           const float* __restrict__ B,
                                           float acc[8][8]) {
    __shared__ float As[16][128];
    __shared__ float Bs[16][128];
    const int tid = threadIdx.x;
    const int lr = tid >> 2;            // 0..63
    const int lk = (tid & 3) * 4;       // 0,4,8,12
    const int tx = tid & 15, ty = tid >> 4;

#pragma unroll
    for (int i = 0; i < 8; i++)
#pragma unroll
        for (int j = 0; j < 8; j++) acc[i][j] = 0.f;

    for (int k0 = 0; k0 < 1024; k0 += 16) {
        __syncthreads();
#pragma unroll
        for (int rr = 0; rr < 128; rr += 64) {
            float4 a = *(const float4*)(A + (size_t)(lr + rr) * 1024 + k0 + lk);
            As[lk + 0][lr + rr] = a.x; As[lk + 1][lr + rr] = a.y;
            As[lk + 2][lr + rr] = a.z; As[lk + 3][lr + rr] = a.w;
            float4 b = *(const float4*)(B + (size_t)(lr + rr) * 1024 + k0 + lk);
            Bs[lk + 0][lr + rr] = b.x; Bs[lk + 1][lr + rr] = b.y;
            Bs[lk + 2][lr + rr] = b.z; Bs[lk + 3][lr + rr] = b.w;
        }
        __syncthreads();
#pragma unroll
        for (int kk = 0; kk < 16; kk++) {
            float a[8], b[8];
            *(float4*)(a)     = *(const float4*)&As[kk][ty * 8];
            *(float4*)(a + 4) = *(const float4*)&As[kk][ty * 8 + 4];
            *(float4*)(b)     = *(const float4*)&Bs[kk][tx * 8];
            *(float4*)(b + 4) = *(const float4*)&Bs[kk][tx * 8 + 4];
#pragma unroll
            for (int i = 0; i < 8; i++)
#pragma unroll
                for (int j = 0; j < 8; j++) acc[i][j] += a[i] * b[j];
        }
    }
}

// ---------------- 2) sim = xn @ xn^T, threshold into byte mask --------------
__global__ __launch_bounds__(256) void sim_kernel() {
    const int bz = blockIdx.z;
    const int m0 = blockIdx.y * 128, n0 = blockIdx.x * 128;
    const float* base = g_xn + (size_t)bz * SEQ * DM;
    float acc[8][8];
    gemm128_nt(base + (size_t)m0 * 1024, base + (size_t)n0 * 1024, acc);

    const int tx = threadIdx.x & 15, ty = threadIdx.x >> 4;
    size_t out = ((size_t)bz * SEQ + m0 + ty * 8) * SEQ + n0 + tx * 8;
#pragma unroll
    for (int i = 0; i < 8; i++) {
        unsigned int lo = 0, hi = 0;
#pragma unroll
        for (int j = 0; j < 4; j++) lo |= (acc[i][j] > 0.7f ? 1u : 0u) << (8 * j);
#pragma unroll
        for (int j = 4; j < 8; j++) hi |= (acc[i][j] > 0.7f ? 1u : 0u) << (8 * (j - 4));
        *(uint2*)(g_mask + out + (size_t)i * SEQ) = make_uint2(lo, hi);
    }
}

// ---------------- 3) projections: Y = x @ W^T + b (z selects Q/K/V) --------
__global__ __launch_bounds__(256) void proj_kernel(const float* __restrict__ x,
        const float* __restrict__ Wq, const float* __restrict__ bq,
        const float* __restrict__ Wk, const float* __restrict__ bk,
        const float* __restrict__ Wv, const float* __restrict__ bv) {
    const float* W; const float* bias; float* Y;
    if (blockIdx.z == 0)      { W = Wq; bias = bq; Y = g_q; }
    else if (blockIdx.z == 1) { W = Wk; bias = bk; Y = g_k; }
    else                      { W = Wv; bias = bv; Y = g_v; }
    const int m0 = blockIdx.y * 128, n0 = blockIdx.x * 128;
    float acc[8][8];
    gemm128_nt(x + (size_t)m0 * 1024, W + (size_t)n0 * 1024, acc);

    const int tx = threadIdx.x & 15, ty = threadIdx.x >> 4;
    float bc[8];
#pragma unroll
    for (int j = 0; j < 8; j++) bc[j] = bias[n0 + tx * 8 + j];
#pragma unroll
    for (int i = 0; i < 8; i++) {
        float* yr = Y + (size_t)(m0 + ty * 8 + i) * 1024 + n0 + tx * 8;
        float4 v0 = make_float4(acc[i][0] + bc[0], acc[i][1] + bc[1],
                                acc[i][2] + bc[2], acc[i][3] + bc[3]);
        float4 v1 = make_float4(acc[i][4] + bc[4], acc[i][5] + bc[5],
                                acc[i][6] + bc[6], acc[i][7] + bc[7]);
        *(float4*)(yr) = v0;
        *(float4*)(yr + 4) = v1;
    }
}

// ---------------- 4) masked flash attention ---------------------------------
// grid (S/64, H, B), 256 threads = 8 warps; warp owns 8 queries.
// lane j handles keys (t0+j, t0+j+32) and output dims (j, j+32).
#define SMEM_ATTN ((64*64 + 64*65 + 64*64 + 8*8*64) * 4)

__global__ __launch_bounds__(256) void attn_kernel(float* __restrict__ out) {
    extern __shared__ float sm[];
    float* Qs = sm;              // [64][64]
    float* Kt = Qs + 64 * 64;    // [64][65] transposed, padded
    float* Vs = Kt + 64 * 65;    // [64][64]
    float* Pb = Vs + 64 * 64;    // [8 warps][8 q][64 k]

    const int b = blockIdx.z, h = blockIdx.y, q0 = blockIdx.x * 64;
    const int tid = threadIdx.x, lane = tid & 31, w = tid >> 5;
    const float* Q = g_q + (size_t)b * SEQ * DM + h * DK;
    const float* K = g_k + (size_t)b * SEQ * DM + h * DK;
    const float* V = g_v + (size_t)b * SEQ * DM + h * DK;
    const unsigned char* Mrow = g_mask + ((size_t)b * SEQ + q0) * SEQ;

    {   // load Q tile
        int r = tid >> 4, c4 = (tid & 15) * 4;
#pragma unroll
        for (int rr = 0; rr < 64; rr += 16) {
            float4 v = *(const float4*)(Q + (size_t)(q0 + r + rr) * DM + c4);
            *(float4*)(Qs + (r + rr) * 64 + c4) = v;
        }
    }

    float m_i[8], l_i[8], o0[8], o1[8];
#pragma unroll
    for (int i = 0; i < 8; i++) { m_i[i] = -1e30f; l_i[i] = 0.f; o0[i] = 0.f; o1[i] = 0.f; }

    float* pw = Pb + w * 512;
    const float scale = 0.125f;   // 1/sqrt(64)

    for (int t0 = 0; t0 < SEQ; t0 += 64) {
        __syncthreads();
        {   // load K (transposed) and V tiles
            int r = tid >> 4, c4 = (tid & 15) * 4;
#pragma unroll
            for (int rr = 0; rr < 64; rr += 16) {
                float4 kv = *(const float4*)(K + (size_t)(t0 + r + rr) * DM + c4);
                Kt[(c4 + 0) * 65 + r + rr] = kv.x;
                Kt[(c4 + 1) * 65 + r + rr] = kv.y;
                Kt[(c4 + 2) * 65 + r + rr] = kv.z;
                Kt[(c4 + 3) * 65 + r + rr] = kv.w;
                float4 vv = *(const float4*)(V + (size_t)(t0 + r + rr) * DM + c4);
                *(float4*)(Vs + (r + rr) * 64 + c4) = vv;
            }
        }
        __syncthreads();

        float s0[8], s1[8];
#pragma unroll
        for (int i = 0; i < 8; i++) { s0[i] = 0.f; s1[i] = 0.f; }
        const float* qrow = Qs + w * 8 * 64;
#pragma unroll 4
        for (int d = 0; d < 64; d++) {
            float k0 = Kt[d * 65 + lane];
            float k1 = Kt[d * 65 + lane + 32];
#pragma unroll
            for (int i = 0; i < 8; i++) {
                float qd = qrow[i * 64 + d];
                s0[i] += qd * k0;
                s1[i] += qd * k1;
            }
        }

#pragma unroll
        for (int i = 0; i < 8; i++) {
            const unsigned char* mr = Mrow + (size_t)(w * 8 + i) * SEQ + t0;
            s0[i] = mr[lane]      ? s0[i] * scale : -1e30f;
            s1[i] = mr[lane + 32] ? s1[i] * scale : -1e30f;
            float mt = fmaxf(s0[i], s1[i]);
#pragma unroll
            for (int o = 16; o; o >>= 1) mt = fmaxf(mt, __shfl_xor_sync(~0u, mt, o));
            float mn = fmaxf(m_i[i], mt);
            float alpha = __expf(m_i[i] - mn);
            float p0 = __expf(s0[i] - mn);
            float p1 = __expf(s1[i] - mn);
            float ps = p0 + p1;
#pragma unroll
            for (int o = 16; o; o >>= 1) ps += __shfl_xor_sync(~0u, ps, o);
            l_i[i] = l_i[i] * alpha + ps;
            m_i[i] = mn;
            o0[i] *= alpha; o1[i] *= alpha;
            pw[i * 64 + lane] = p0;
            pw[i * 64 + lane + 32] = p1;
        }
        __syncwarp();
#pragma unroll 2
        for (int j = 0; j < 64; j++) {
            float v0 = Vs[j * 64 + lane];
            float v1 = Vs[j * 64 + lane + 32];
#pragma unroll
            for (int i = 0; i < 8; i++) {
                float p = pw[i * 64 + j];
                o0[i] += p * v0;
                o1[i] += p * v1;
            }
        }
        __syncwarp();
    }

    float* ob = out + (((size_t)b * NH + h) * SEQ + q0 + w * 8) * DK;
#pragma unroll
    for (int i = 0; i < 8; i++) {
        float invl = 1.0f / l_i[i];
        ob[i * DK + lane]      = o0[i] * invl;
        ob[i * DK + lane + 32] = o1[i] * invl;
    }
}

// ---------------- launch ----------------------------------------------------
extern "C" void kernel_launch(void* const* d_in, const int* in_sizes, int n_in,
                              void* d_out, int out_size) {
    const float* x  = (const float*)d_in[0];
    const float* Wq = (const float*)d_in[1];
    const float* bq = (const float*)d_in[2];
    const float* Wk = (const float*)d_in[3];
    const float* bk = (const float*)d_in[4];
    const float* Wv = (const float*)d_in[5];
    const float* bv = (const float*)d_in[6];
    float* out = (float*)d_out;

    norm_kernel<<<BATCH * SEQ, 256>>>(x);
    sim_kernel<<<dim3(SEQ / 128, SEQ / 128, BATCH), 256>>>();
    proj_kernel<<<dim3(DM / 128, (BATCH * SEQ) / 128, 3), 256>>>(x, Wq, bq, Wk, bk, Wv, bv);

    cudaFuncSetAttribute(attn_kernel, cudaFuncAttributeMaxDynamicSharedMemorySize, SMEM_ATTN);
    attn_kernel<<<dim3(SEQ / 64, NH, BATCH), 256, SMEM_ATTN>>>(out);
}

// round 3
// speedup vs baseline: 1.9614x; 1.9614x over previous
#include <cuda_runtime.h>

#define BATCH 2
#define SEQ   2048
#define DM    1024
#define NH    16
#define DK    64

// ---------------- scratch (allocation-free: device globals) ----------------
__device__ float g_xn[BATCH * SEQ * DM];          // normalized x
__device__ float g_q[BATCH * SEQ * DM];
__device__ float g_k[BATCH * SEQ * DM];
__device__ float g_v[BATCH * SEQ * DM];
__device__ unsigned char g_mask[BATCH * SEQ * SEQ];   // 1 byte per (b,s,t)
__device__ unsigned short g_idx[(size_t)BATCH * SEQ * SEQ]; // per-row key lists
__device__ int g_cnt[BATCH * SEQ];                    // per-row key counts

// ---------------- 1) row normalization ----------------
__global__ __launch_bounds__(256) void norm_kernel(const float* __restrict__ x) {
    int row = blockIdx.x;                 // 0..B*S-1
    int t = threadIdx.x;
    const float4* xr = (const float4*)(x + (size_t)row * DM);
    float4* xo = (float4*)(g_xn + (size_t)row * DM);
    float4 v = xr[t];                     // 256 threads * 4 = 1024
    float ss = v.x * v.x + v.y * v.y + v.z * v.z + v.w * v.w;
    __shared__ float red[8];
#pragma unroll
    for (int o = 16; o; o >>= 1) ss += __shfl_xor_sync(~0u, ss, o);
    if ((t & 31) == 0) red[t >> 5] = ss;
    __syncthreads();
    if (t < 8) {
        float s = red[t];
#pragma unroll
        for (int o = 4; o; o >>= 1) s += __shfl_xor_sync(0xffu, s, o);
        if (t == 0) red[0] = s;
    }
    __syncthreads();
    float inv = 1.0f / fmaxf(sqrtf(red[0]), 1e-12f);
    v.x *= inv; v.y *= inv; v.z *= inv; v.w *= inv;
    xo[t] = v;
}

// ---------------- shared GEMM tile: C[128x128] = A(Mx1024) * B(Nx1024)^T ----
__device__ __forceinline__ void gemm128_nt(const float* __restrict__ A,
                                           const float* __restrict__ B,
                                           float acc[8][8]) {
    __shared__ float As[16][128];
    __shared__ float Bs[16][128];
    const int tid = threadIdx.x;
    const int lr = tid >> 2;            // 0..63
    const int lk = (tid & 3) * 4;       // 0,4,8,12
    const int tx = tid & 15, ty = tid >> 4;

#pragma unroll
    for (int i = 0; i < 8; i++)
#pragma unroll
        for (int j = 0; j < 8; j++) acc[i][j] = 0.f;

    for (int k0 = 0; k0 < 1024; k0 += 16) {
        __syncthreads();
#pragma unroll
        for (int rr = 0; rr < 128; rr += 64) {
            float4 a = *(const float4*)(A + (size_t)(lr + rr) * 1024 + k0 + lk);
            As[lk + 0][lr + rr] = a.x; As[lk + 1][lr + rr] = a.y;
            As[lk + 2][lr + rr] = a.z; As[lk + 3][lr + rr] = a.w;
            float4 b = *(const float4*)(B + (size_t)(lr + rr) * 1024 + k0 + lk);
            Bs[lk + 0][lr + rr] = b.x; Bs[lk + 1][lr + rr] = b.y;
            Bs[lk + 2][lr + rr] = b.z; Bs[lk + 3][lr + rr] = b.w;
        }
        __syncthreads();
#pragma unroll
        for (int kk = 0; kk < 16; kk++) {
            float a[8], b[8];
            *(float4*)(a)     = *(const float4*)&As[kk][ty * 8];
            *(float4*)(a + 4) = *(const float4*)&As[kk][ty * 8 + 4];
            *(float4*)(b)     = *(const float4*)&Bs[kk][tx * 8];
            *(float4*)(b + 4) = *(const float4*)&Bs[kk][tx * 8 + 4];
#pragma unroll
            for (int i = 0; i < 8; i++)
#pragma unroll
                for (int j = 0; j < 8; j++) acc[i][j] += a[i] * b[j];
        }
    }
}

// ---------------- 2) sim = xn @ xn^T, threshold into byte mask --------------
__global__ __launch_bounds__(256) void sim_kernel() {
    const int bz = blockIdx.z;
    const int m0 = blockIdx.y * 128, n0 = blockIdx.x * 128;
    const float* base = g_xn + (size_t)bz * SEQ * DM;
    float acc[8][8];
    gemm128_nt(base + (size_t)m0 * 1024, base + (size_t)n0 * 1024, acc);

    const int tx = threadIdx.x & 15, ty = threadIdx.x >> 4;
    size_t out = ((size_t)bz * SEQ + m0 + ty * 8) * SEQ + n0 + tx * 8;
#pragma unroll
    for (int i = 0; i < 8; i++) {
        unsigned int lo = 0, hi = 0;
#pragma unroll
        for (int j = 0; j < 4; j++) lo |= (acc[i][j] > 0.7f ? 1u : 0u) << (8 * j);
#pragma unroll
        for (int j = 4; j < 8; j++) hi |= (acc[i][j] > 0.7f ? 1u : 0u) << (8 * (j - 4));
        *(uint2*)(g_mask + out + (size_t)i * SEQ) = make_uint2(lo, hi);
    }
}

// ---------------- 2b) compact mask rows into index lists --------------------
// one warp per (b,s) row; ballot compaction preserves correctness for any mask
__global__ __launch_bounds__(256) void build_idx_kernel() {
    int row = blockIdx.x * 8 + (threadIdx.x >> 5);
    int lane = threadIdx.x & 31;
    const unsigned* mrow = (const unsigned*)(g_mask + (size_t)row * SEQ);
    unsigned short* lst = g_idx + (size_t)row * SEQ;
    int count = 0;
#pragma unroll 4
    for (int it = 0; it < 16; ++it) {          // 16 * 32 lanes * 4 bytes = 2048
        unsigned m4 = mrow[it * 32 + lane];
#pragma unroll
        for (int sub = 0; sub < 4; ++sub) {
            bool pred = ((m4 >> (8 * sub)) & 0xffu) != 0u;
            unsigned bal = __ballot_sync(~0u, pred);
            if (pred) {
                int pos = count + __popc(bal & ((1u << lane) - 1u));
                lst[pos] = (unsigned short)((it * 32 + lane) * 4 + sub);
            }
            count += __popc(bal);
        }
    }
    if (lane == 0) g_cnt[row] = count;
}

// ---------------- 3) projections: Y = x @ W^T + b (z selects Q/K/V) --------
__global__ __launch_bounds__(256) void proj_kernel(const float* __restrict__ x,
        const float* __restrict__ Wq, const float* __restrict__ bq,
        const float* __restrict__ Wk, const float* __restrict__ bk,
        const float* __restrict__ Wv, const float* __restrict__ bv) {
    const float* W; const float* bias; float* Y;
    if (blockIdx.z == 0)      { W = Wq; bias = bq; Y = g_q; }
    else if (blockIdx.z == 1) { W = Wk; bias = bk; Y = g_k; }
    else                      { W = Wv; bias = bv; Y = g_v; }
    const int m0 = blockIdx.y * 128, n0 = blockIdx.x * 128;
    float acc[8][8];
    gemm128_nt(x + (size_t)m0 * 1024, W + (size_t)n0 * 1024, acc);

    const int tx = threadIdx.x & 15, ty = threadIdx.x >> 4;
    float bc[8];
#pragma unroll
    for (int j = 0; j < 8; j++) bc[j] = bias[n0 + tx * 8 + j];
#pragma unroll
    for (int i = 0; i < 8; i++) {
        float* yr = Y + (size_t)(m0 + ty * 8 + i) * 1024 + n0 + tx * 8;
        float4 v0 = make_float4(acc[i][0] + bc[0], acc[i][1] + bc[1],
                                acc[i][2] + bc[2], acc[i][3] + bc[3]);
        float4 v1 = make_float4(acc[i][4] + bc[4], acc[i][5] + bc[5],
                                acc[i][6] + bc[6], acc[i][7] + bc[7]);
        *(float4*)(yr) = v0;
        *(float4*)(yr + 4) = v1;
    }
}

// ---------------- 4) sparse masked attention ---------------------------------
// warp per (row, head). cnt==1 fast path: softmax of a single element is 1,
// so output is a pure gather of the v row. General path: online softmax over
// 32-key chunks (lane=key for scores, then shfl-broadcast p, lane=dim for PV).
__global__ __launch_bounds__(256) void attn_sparse_kernel(float* __restrict__ out) {
    __shared__ float qsm[8][64];
    const int w = threadIdx.x >> 5, lane = threadIdx.x & 31;
    const int gw = blockIdx.x * 8 + w;            // 0 .. B*S*NH-1
    const int h = gw & (NH - 1);
    const int row = gw >> 4;                      // b*SEQ + s
    const int b = row >> 11, s = row & (SEQ - 1);

    const int cnt = g_cnt[row];
    const unsigned short* lst = g_idx + (size_t)row * SEQ;
    float* ob = out + (((size_t)b * NH + h) * SEQ + s) * DK;
    const float* Vb = g_v + (size_t)b * SEQ * DM + h * DK;

    if (cnt == 1) {
        const float* vp = Vb + (size_t)lst[0] * DM;
        ob[lane]      = vp[lane];
        ob[lane + 32] = vp[lane + 32];
        return;
    }

    const float* Kb = g_k + (size_t)b * SEQ * DM + h * DK;
    const float* qp = g_q + ((size_t)b * SEQ + s) * DM + h * DK;
    float* qs = qsm[w];
    qs[lane] = qp[lane];
    qs[lane + 32] = qp[lane + 32];
    __syncwarp();

    float m = -1e30f, l = 0.f, o0 = 0.f, o1 = 0.f;
    for (int c0 = 0; c0 < cnt; c0 += 32) {
        int ci = c0 + lane;
        int tj = (ci < cnt) ? (int)lst[ci] : -1;
        float sc = -1e30f;
        if (tj >= 0) {
            const float* kp = Kb + (size_t)tj * DM;
            float acc = 0.f;
#pragma unroll
            for (int d = 0; d < 64; d += 4) {
                float4 kq = *(const float4*)(kp + d);
                float4 qq = *(const float4*)(qs + d);
                acc += kq.x * qq.x + kq.y * qq.y + kq.z * qq.z + kq.w * qq.w;
            }
            sc = acc * 0.125f;                    // 1/sqrt(64)
        }
        float mt = sc;
#pragma unroll
        for (int o = 16; o; o >>= 1) mt = fmaxf(mt, __shfl_xor_sync(~0u, mt, o));
        float mn = fmaxf(m, mt);
        float alpha = __expf(m - mn);
        float p = __expf(sc - mn);                // 0 for invalid lanes
        float ps = p;
#pragma unroll
        for (int o = 16; o; o >>= 1) ps += __shfl_xor_sync(~0u, ps, o);
        l = l * alpha + ps;
        o0 *= alpha; o1 *= alpha;
        m = mn;
        int nk = min(32, cnt - c0);
        for (int j = 0; j < nk; ++j) {
            float pj = __shfl_sync(~0u, p, j);
            int t = __shfl_sync(~0u, tj, j);
            const float* vp = Vb + (size_t)t * DM;
            o0 += pj * vp[lane];
            o1 += pj * vp[lane + 32];
        }
    }
    float invl = 1.0f / l;
    ob[lane]      = o0 * invl;
    ob[lane + 32] = o1 * invl;
}

// ---------------- launch ----------------------------------------------------
extern "C" void kernel_launch(void* const* d_in, const int* in_sizes, int n_in,
                              void* d_out, int out_size) {
    const float* x  = (const float*)d_in[0];
    const float* Wq = (const float*)d_in[1];
    const float* bq = (const float*)d_in[2];
    const float* Wk = (const float*)d_in[3];
    const float* bk = (const float*)d_in[4];
    const float* Wv = (const float*)d_in[5];
    const float* bv = (const float*)d_in[6];
    float* out = (float*)d_out;

    norm_kernel<<<BATCH * SEQ, 256>>>(x);
    sim_kernel<<<dim3(SEQ / 128, SEQ / 128, BATCH), 256>>>();
    build_idx_kernel<<<(BATCH * SEQ) / 8, 256>>>();
    proj_kernel<<<dim3(DM / 128, (BATCH * SEQ) / 128, 3), 256>>>(x, Wq, bq, Wk, bk, Wv, bv);
    attn_sparse_kernel<<<(BATCH * SEQ * NH) / 8, 256>>>(out);
}

// round 5
// speedup vs baseline: 4.9344x; 2.5158x over previous
#include <cuda_runtime.h>
#include <cuda_bf16.h>
#include <cstdint>

#define BATCH 2
#define SEQ   2048
#define DM    1024
#define NH    16
#define DK    64

// ---------------- scratch (allocation-free: device globals) ----------------
__device__ __nv_bfloat16 g_xnhi[BATCH * SEQ * DM];   // normalized x, bf16
__device__ __nv_bfloat16 g_xhi[BATCH * SEQ * DM];    // x hi
__device__ __nv_bfloat16 g_xlo[BATCH * SEQ * DM];    // x lo
__device__ __nv_bfloat16 g_whi[3][DM * DM];          // Wq/Wk/Wv hi
__device__ __nv_bfloat16 g_wlo[3][DM * DM];          // Wq/Wk/Wv lo
__device__ float g_q[BATCH * SEQ * DM];
__device__ float g_k[BATCH * SEQ * DM];
__device__ float g_v[BATCH * SEQ * DM];
__device__ unsigned char g_mask[BATCH * SEQ * SEQ];
__device__ unsigned short g_idx[(size_t)BATCH * SEQ * SEQ];
__device__ int g_cnt[BATCH * SEQ];

// ---------------- PTX helpers (sm_80-class: valid at base sm_103 target) ----
__device__ __forceinline__ uint32_t smem_u32(const void* p) {
    uint32_t a;
    asm("{ .reg .u64 t; cvta.to.shared.u64 t, %1; cvt.u32.u64 %0, t; }" : "=r"(a) : "l"(p));
    return a;
}
#define CP_ASYNC16(dst, src) \
    asm volatile("cp.async.cg.shared.global [%0], [%1], 16;" :: "r"(dst), "l"(src))
#define CP_COMMIT() asm volatile("cp.async.commit_group;" ::: "memory")
#define CP_WAIT1()  asm volatile("cp.async.wait_group 1;" ::: "memory")
#define CP_WAIT0()  asm volatile("cp.async.wait_group 0;" ::: "memory")

__device__ __forceinline__ void ldsm4(uint32_t* r, uint32_t addr) {
    asm volatile("ldmatrix.sync.aligned.m8n8.x4.shared.b16 {%0,%1,%2,%3}, [%4];"
                 : "=r"(r[0]), "=r"(r[1]), "=r"(r[2]), "=r"(r[3]) : "r"(addr));
}
__device__ __forceinline__ void mma16816(float* c, const uint32_t* a, uint32_t b0, uint32_t b1) {
    asm volatile("mma.sync.aligned.m16n8k16.row.col.f32.bf16.bf16.f32 "
                 "{%0,%1,%2,%3}, {%4,%5,%6,%7}, {%8,%9}, {%0,%1,%2,%3};"
                 : "+f"(c[0]), "+f"(c[1]), "+f"(c[2]), "+f"(c[3])
                 : "r"(a[0]), "r"(a[1]), "r"(a[2]), "r"(a[3]), "r"(b0), "r"(b1));
}

// ---------------- 1) norm + hi/lo split ----------------
__global__ __launch_bounds__(256) void norm_kernel(const float* __restrict__ x) {
    int row = blockIdx.x, t = threadIdx.x;
    float4 v = ((const float4*)(x + (size_t)row * DM))[t];

    __nv_bfloat16 h0 = __float2bfloat16_rn(v.x), h1 = __float2bfloat16_rn(v.y);
    __nv_bfloat16 h2 = __float2bfloat16_rn(v.z), h3 = __float2bfloat16_rn(v.w);
    ((ushort4*)(g_xhi + (size_t)row * DM))[t] = make_ushort4(
        __bfloat16_as_ushort(h0), __bfloat16_as_ushort(h1),
        __bfloat16_as_ushort(h2), __bfloat16_as_ushort(h3));
    ((ushort4*)(g_xlo + (size_t)row * DM))[t] = make_ushort4(
        __bfloat16_as_ushort(__float2bfloat16_rn(v.x - __bfloat162float(h0))),
        __bfloat16_as_ushort(__float2bfloat16_rn(v.y - __bfloat162float(h1))),
        __bfloat16_as_ushort(__float2bfloat16_rn(v.z - __bfloat162float(h2))),
        __bfloat16_as_ushort(__float2bfloat16_rn(v.w - __bfloat162float(h3))));

    float ss = v.x * v.x + v.y * v.y + v.z * v.z + v.w * v.w;
    __shared__ float red[8];
#pragma unroll
    for (int o = 16; o; o >>= 1) ss += __shfl_xor_sync(~0u, ss, o);
    if ((t & 31) == 0) red[t >> 5] = ss;
    __syncthreads();
    if (t < 8) {
        float s = red[t];
#pragma unroll
        for (int o = 4; o; o >>= 1) s += __shfl_xor_sync(0xffu, s, o);
        if (t == 0) red[0] = s;
    }
    __syncthreads();
    float inv = 1.0f / fmaxf(sqrtf(red[0]), 1e-12f);
    ((ushort4*)(g_xnhi + (size_t)row * DM))[t] = make_ushort4(
        __bfloat16_as_ushort(__float2bfloat16_rn(v.x * inv)),
        __bfloat16_as_ushort(__float2bfloat16_rn(v.y * inv)),
        __bfloat16_as_ushort(__float2bfloat16_rn(v.z * inv)),
        __bfloat16_as_ushort(__float2bfloat16_rn(v.w * inv)));
}

// ---------------- 1b) weight hi/lo split ----------------
__global__ __launch_bounds__(256) void convw_kernel(const float* __restrict__ Wq,
        const float* __restrict__ Wk, const float* __restrict__ Wv) {
    int z = blockIdx.y;
    const float* W = (z == 0) ? Wq : (z == 1) ? Wk : Wv;
    size_t i = (size_t)blockIdx.x * 1024 + threadIdx.x * 4;
    float4 v = *(const float4*)(W + i);
    __nv_bfloat16 h0 = __float2bfloat16_rn(v.x), h1 = __float2bfloat16_rn(v.y);
    __nv_bfloat16 h2 = __float2bfloat16_rn(v.z), h3 = __float2bfloat16_rn(v.w);
    *(ushort4*)(g_whi[z] + i) = make_ushort4(
        __bfloat16_as_ushort(h0), __bfloat16_as_ushort(h1),
        __bfloat16_as_ushort(h2), __bfloat16_as_ushort(h3));
    *(ushort4*)(g_wlo[z] + i) = make_ushort4(
        __bfloat16_as_ushort(__float2bfloat16_rn(v.x - __bfloat162float(h0))),
        __bfloat16_as_ushort(__float2bfloat16_rn(v.y - __bfloat162float(h1))),
        __bfloat16_as_ushort(__float2bfloat16_rn(v.z - __bfloat162float(h2))),
        __bfloat16_as_ushort(__float2bfloat16_rn(v.w - __bfloat162float(h3))));
}

// ---------------- HMMA GEMM core: 128x128 CTA tile, BK=32, double-buffered --
// Both A and B are [rows][K=1024] bf16, K-contiguous. C = A * B^T.
// 8 warps: wm = wid&1 (m 0/64), wn = wid>>1 (n 0/32/64/96). Warp tile 64x32.
#define LDSR 40                 // padded smem row: 40 bf16 = 80 B
#define SBUF (128 * LDSR)       // one buffer: 5120 bf16

struct GSmem { __nv_bfloat16 A[2 * SBUF]; __nv_bfloat16 B[2 * SBUF]; };

__device__ __forceinline__ void g_load(const __nv_bfloat16* const* Aps,
                                       const __nv_bfloat16* const* Bps,
                                       uint32_t sA, uint32_t sB, int kt) {
    const int p = kt >> 5, kk = (kt & 31) * 32, buf = kt & 1;
    const __nv_bfloat16* Ag = Aps[p] + kk;
    const __nv_bfloat16* Bg = Bps[p] + kk;
#pragma unroll
    for (int h = 0; h < 2; h++) {
        int id = threadIdx.x + h * 256;     // 0..511
        int row = id >> 2, c8 = (id & 3) * 8;
        uint32_t so = (uint32_t)(buf * SBUF + row * LDSR + c8) * 2;
        CP_ASYNC16(sA + so, Ag + (size_t)row * DM + c8);
        CP_ASYNC16(sB + so, Bg + (size_t)row * DM + c8);
    }
}

__device__ __forceinline__ void g_compute(uint32_t sA, uint32_t sB, int buf,
                                          int wm, int wn, int lane,
                                          float acc[4][4][4]) {
#pragma unroll
    for (int ks = 0; ks < 2; ks++) {
        const int col = ks * 16 + (lane >> 4) * 8;
        uint32_t af[4][4], bf[2][4];
#pragma unroll
        for (int mt = 0; mt < 4; mt++) {
            int row = wm * 64 + mt * 16 + (lane & 15);
            ldsm4(af[mt], sA + (uint32_t)(buf * SBUF + row * LDSR + col) * 2);
        }
#pragma unroll
        for (int nt2 = 0; nt2 < 2; nt2++) {
            int row = wn * 32 + nt2 * 16 + (lane & 15);
            ldsm4(bf[nt2], sB + (uint32_t)(buf * SBUF + row * LDSR + col) * 2);
        }
#pragma unroll
        for (int mt = 0; mt < 4; mt++)
#pragma unroll
            for (int nt = 0; nt < 4; nt++) {
                uint32_t b0 = (nt & 1) ? bf[nt >> 1][1] : bf[nt >> 1][0];
                uint32_t b1 = (nt & 1) ? bf[nt >> 1][3] : bf[nt >> 1][2];
                mma16816(acc[mt][nt], af[mt], b0, b1);
            }
    }
}

__device__ __forceinline__ void g_mainloop(const __nv_bfloat16* const* Aps,
                                           const __nv_bfloat16* const* Bps,
                                           int npass, GSmem* sm,
                                           float acc[4][4][4]) {
    const uint32_t sA = smem_u32(sm->A), sB = smem_u32(sm->B);
    const int lane = threadIdx.x & 31, wid = threadIdx.x >> 5;
    const int wm = wid & 1, wn = wid >> 1;
#pragma unroll
    for (int mt = 0; mt < 4; mt++)
#pragma unroll
        for (int nt = 0; nt < 4; nt++)
#pragma unroll
            for (int r = 0; r < 4; r++) acc[mt][nt][r] = 0.f;

    const int KT = npass * 32;
    g_load(Aps, Bps, sA, sB, 0);
    CP_COMMIT();
    for (int kt = 0; kt < KT; kt++) {
        if (kt + 1 < KT) {
            g_load(Aps, Bps, sA, sB, kt + 1);
            CP_COMMIT();
            CP_WAIT1();
        } else {
            CP_WAIT0();
        }
        __syncthreads();
        g_compute(sA, sB, kt & 1, wm, wn, lane, acc);
        __syncthreads();
    }
}

// ---------------- 2) sim = xn @ xn^T -> threshold -> mask -------------------
__global__ __launch_bounds__(256, 2) void sim_kernel() {
    __shared__ GSmem sm;
    const int bz = blockIdx.z;
    const int m0 = blockIdx.y * 128, n0 = blockIdx.x * 128;
    const __nv_bfloat16* A = g_xnhi + ((size_t)bz * SEQ + m0) * DM;
    const __nv_bfloat16* B = g_xnhi + ((size_t)bz * SEQ + n0) * DM;
    const __nv_bfloat16* Aps[3] = {A, A, A};
    const __nv_bfloat16* Bps[3] = {B, B, B};
    float acc[4][4][4];
    g_mainloop(Aps, Bps, 1, &sm, acc);

    const int lane = threadIdx.x & 31, wid = threadIdx.x >> 5;
    const int wm = wid & 1, wn = wid >> 1;
    const int mb = m0 + wm * 64 + (lane >> 2);
    const int nb = n0 + wn * 32 + (lane & 3) * 2;
#pragma unroll
    for (int mt = 0; mt < 4; mt++)
#pragma unroll
        for (int rh = 0; rh < 2; rh++) {
            size_t ro = ((size_t)bz * SEQ + mb + mt * 16 + rh * 8) * SEQ;
#pragma unroll
            for (int nt = 0; nt < 4; nt++) {
                unsigned short u =
                    (acc[mt][nt][rh * 2 + 0] > 0.7f ? 1u : 0u) |
                    ((acc[mt][nt][rh * 2 + 1] > 0.7f ? 1u : 0u) << 8);
                *(unsigned short*)(g_mask + ro + nb + nt * 8) = u;
            }
        }
}

// ---------------- 3) projections: hi/lo 3-pass (K=3072) + bias --------------
__global__ __launch_bounds__(256, 2) void proj_kernel(const float* __restrict__ bq,
        const float* __restrict__ bk, const float* __restrict__ bv) {
    __shared__ GSmem sm;
    const int z = blockIdx.z;
    const int m0 = blockIdx.y * 128, n0 = blockIdx.x * 128;
    const float* bias = (z == 0) ? bq : (z == 1) ? bk : bv;
    float* Y = (z == 0) ? g_q : (z == 1) ? g_k : g_v;

    const __nv_bfloat16* Aps[3] = {g_xhi + (size_t)m0 * DM, g_xlo + (size_t)m0 * DM,
                                   g_xhi + (size_t)m0 * DM};
    const __nv_bfloat16* Bps[3] = {g_whi[z] + (size_t)n0 * DM, g_whi[z] + (size_t)n0 * DM,
                                   g_wlo[z] + (size_t)n0 * DM};
    float acc[4][4][4];
    g_mainloop(Aps, Bps, 3, &sm, acc);

    const int lane = threadIdx.x & 31, wid = threadIdx.x >> 5;
    const int wm = wid & 1, wn = wid >> 1;
    const int mb = m0 + wm * 64 + (lane >> 2);
    const int nb = n0 + wn * 32 + (lane & 3) * 2;
    float2 bv2[4];
#pragma unroll
    for (int nt = 0; nt < 4; nt++)
        bv2[nt] = make_float2(__ldg(bias + nb + nt * 8), __ldg(bias + nb + nt * 8 + 1));
#pragma unroll
    for (int mt = 0; mt < 4; mt++)
#pragma unroll
        for (int rh = 0; rh < 2; rh++) {
            float* yr = Y + (size_t)(mb + mt * 16 + rh * 8) * DM;
#pragma unroll
            for (int nt = 0; nt < 4; nt++) {
                float2 o = make_float2(acc[mt][nt][rh * 2 + 0] + bv2[nt].x,
                                       acc[mt][nt][rh * 2 + 1] + bv2[nt].y);
                *(float2*)(yr + nb + nt * 8) = o;
            }
        }
}

// ---------------- 2b) compact mask rows into index lists --------------------
__global__ __launch_bounds__(256) void build_idx_kernel() {
    int row = blockIdx.x * 8 + (threadIdx.x >> 5);
    int lane = threadIdx.x & 31;
    const unsigned* mrow = (const unsigned*)(g_mask + (size_t)row * SEQ);
    unsigned short* lst = g_idx + (size_t)row * SEQ;
    int count = 0;
#pragma unroll 4
    for (int it = 0; it < 16; ++it) {
        unsigned m4 = mrow[it * 32 + lane];
#pragma unroll
        for (int sub = 0; sub < 4; ++sub) {
            bool pred = ((m4 >> (8 * sub)) & 0xffu) != 0u;
            unsigned bal = __ballot_sync(~0u, pred);
            if (pred) {
                int pos = count + __popc(bal & ((1u << lane) - 1u));
                lst[pos] = (unsigned short)((it * 32 + lane) * 4 + sub);
            }
            count += __popc(bal);
        }
    }
    if (lane == 0) g_cnt[row] = count;
}

// ---------------- 4) sparse masked attention --------------------------------
__global__ __launch_bounds__(256) void attn_sparse_kernel(float* __restrict__ out) {
    __shared__ float qsm[8][64];
    const int w = threadIdx.x >> 5, lane = threadIdx.x & 31;
    const int gw = blockIdx.x * 8 + w;
    const int h = gw & (NH - 1);
    const int row = gw >> 4;
    const int b = row >> 11, s = row & (SEQ - 1);

    const int cnt = g_cnt[row];
    const unsigned short* lst = g_idx + (size_t)row * SEQ;
    float* ob = out + (((size_t)b * NH + h) * SEQ + s) * DK;
    const float* Vb = g_v + (size_t)b * SEQ * DM + h * DK;

    if (cnt == 1) {
        const float* vp = Vb + (size_t)lst[0] * DM;
        ob[lane]      = vp[lane];
        ob[lane + 32] = vp[lane + 32];
        return;
    }

    const float* Kb = g_k + (size_t)b * SEQ * DM + h * DK;
    const float* qp = g_q + ((size_t)b * SEQ + s) * DM + h * DK;
    float* qs = qsm[w];
    qs[lane] = qp[lane];
    qs[lane + 32] = qp[lane + 32];
    __syncwarp();

    float m = -1e30f, l = 0.f, o0 = 0.f, o1 = 0.f;
    for (int c0 = 0; c0 < cnt; c0 += 32) {
        int ci = c0 + lane;
        int tj = (ci < cnt) ? (int)lst[ci] : -1;
        float sc = -1e30f;
        if (tj >= 0) {
            const float* kp = Kb + (size_t)tj * DM;
            float a = 0.f;
#pragma unroll
            for (int d = 0; d < 64; d += 4) {
                float4 kq = *(const float4*)(kp + d);
                float4 qq = *(const float4*)(qs + d);
                a += kq.x * qq.x + kq.y * qq.y + kq.z * qq.z + kq.w * qq.w;
            }
            sc = a * 0.125f;
        }
        float mt = sc;
#pragma unroll
        for (int o = 16; o; o >>= 1) mt = fmaxf(mt, __shfl_xor_sync(~0u, mt, o));
        float mn = fmaxf(m, mt);
        float alpha = __expf(m - mn);
        float p = __expf(sc - mn);
        float ps = p;
#pragma unroll
        for (int o = 16; o; o >>= 1) ps += __shfl_xor_sync(~0u, ps, o);
        l = l * alpha + ps;
        o0 *= alpha; o1 *= alpha;
        m = mn;
        int nk = min(32, cnt - c0);
        for (int j = 0; j < nk; ++j) {
            float pj = __shfl_sync(~0u, p, j);
            int t = __shfl_sync(~0u, tj, j);
            const float* vp = Vb + (size_t)t * DM;
            o0 += pj * vp[lane];
            o1 += pj * vp[lane + 32];
        }
    }
    float invl = 1.0f / l;
    ob[lane]      = o0 * invl;
    ob[lane + 32] = o1 * invl;
}

// ---------------- launch ----------------------------------------------------
extern "C" void kernel_launch(void* const* d_in, const int* in_sizes, int n_in,
                              void* d_out, int out_size) {
    const float* x  = (const float*)d_in[0];
    const float* Wq = (const float*)d_in[1];
    const float* bq = (const float*)d_in[2];
    const float* Wk = (const float*)d_in[3];
    const float* bk = (const float*)d_in[4];
    const float* Wv = (const float*)d_in[5];
    const float* bv = (const float*)d_in[6];
    float* out = (float*)d_out;

    norm_kernel<<<BATCH * SEQ, 256>>>(x);
    convw_kernel<<<dim3(DM * DM / 1024, 3), 256>>>(Wq, Wk, Wv);
    sim_kernel<<<dim3(SEQ / 128, SEQ / 128, BATCH), 256>>>();
    build_idx_kernel<<<(BATCH * SEQ) / 8, 256>>>();
    proj_kernel<<<dim3(DM / 128, (BATCH * SEQ) / 128, 3), 256>>>(bq, bk, bv);
    attn_sparse_kernel<<<(BATCH * SEQ * NH) / 8, 256>>>(out);
}

// round 6
// speedup vs baseline: 4.9383x; 1.0008x over previous
#include <cuda_runtime.h>
#include <cuda_bf16.h>
#include <cstdint>

#define BATCH 2
#define SEQ   2048
#define DM    1024
#define NH    16
#define DK    64

// ---------------- scratch (allocation-free: device globals) ----------------
__device__ __nv_bfloat16 g_xnhi[BATCH * SEQ * DM];   // normalized x, bf16
__device__ __nv_bfloat16 g_xhi[BATCH * SEQ * DM];    // x hi
__device__ __nv_bfloat16 g_xlo[BATCH * SEQ * DM];    // x lo
__device__ __nv_bfloat16 g_whi[3][DM * DM];          // Wq/Wk/Wv hi
__device__ __nv_bfloat16 g_wlo[3][DM * DM];          // Wq/Wk/Wv lo
__device__ float g_q[BATCH * SEQ * DM];
__device__ float g_k[BATCH * SEQ * DM];
__device__ float g_v[BATCH * SEQ * DM];
__device__ unsigned char g_mask[BATCH * SEQ * SEQ];
__device__ unsigned short g_idx[(size_t)BATCH * SEQ * SEQ];
__device__ int g_cnt[BATCH * SEQ];

// ---------------- PTX helpers (sm_80-class: valid at base sm_103 target) ----
__device__ __forceinline__ uint32_t smem_u32(const void* p) {
    uint32_t a;
    asm("{ .reg .u64 t; cvta.to.shared.u64 t, %1; cvt.u32.u64 %0, t; }" : "=r"(a) : "l"(p));
    return a;
}
#define CP_ASYNC16(dst, src) \
    asm volatile("cp.async.cg.shared.global [%0], [%1], 16;" :: "r"(dst), "l"(src))
#define CP_COMMIT() asm volatile("cp.async.commit_group;" ::: "memory")
#define CP_WAIT1()  asm volatile("cp.async.wait_group 1;" ::: "memory")
#define CP_WAIT0()  asm volatile("cp.async.wait_group 0;" ::: "memory")

__device__ __forceinline__ void ldsm4(uint32_t* r, uint32_t addr) {
    asm volatile("ldmatrix.sync.aligned.m8n8.x4.shared.b16 {%0,%1,%2,%3}, [%4];"
                 : "=r"(r[0]), "=r"(r[1]), "=r"(r[2]), "=r"(r[3]) : "r"(addr));
}
__device__ __forceinline__ void mma16816(float* c, const uint32_t* a, uint32_t b0, uint32_t b1) {
    asm volatile("mma.sync.aligned.m16n8k16.row.col.f32.bf16.bf16.f32 "
                 "{%0,%1,%2,%3}, {%4,%5,%6,%7}, {%8,%9}, {%0,%1,%2,%3};"
                 : "+f"(c[0]), "+f"(c[1]), "+f"(c[2]), "+f"(c[3])
                 : "r"(a[0]), "r"(a[1]), "r"(a[2]), "r"(a[3]), "r"(b0), "r"(b1));
}

// ---------------- 1) norm + hi/lo split ----------------
__global__ __launch_bounds__(256) void norm_kernel(const float* __restrict__ x) {
    int row = blockIdx.x, t = threadIdx.x;
    float4 v = ((const float4*)(x + (size_t)row * DM))[t];

    __nv_bfloat16 h0 = __float2bfloat16_rn(v.x), h1 = __float2bfloat16_rn(v.y);
    __nv_bfloat16 h2 = __float2bfloat16_rn(v.z), h3 = __float2bfloat16_rn(v.w);
    ((ushort4*)(g_xhi + (size_t)row * DM))[t] = make_ushort4(
        __bfloat16_as_ushort(h0), __bfloat16_as_ushort(h1),
        __bfloat16_as_ushort(h2), __bfloat16_as_ushort(h3));
    ((ushort4*)(g_xlo + (size_t)row * DM))[t] = make_ushort4(
        __bfloat16_as_ushort(__float2bfloat16_rn(v.x - __bfloat162float(h0))),
        __bfloat16_as_ushort(__float2bfloat16_rn(v.y - __bfloat162float(h1))),
        __bfloat16_as_ushort(__float2bfloat16_rn(v.z - __bfloat162float(h2))),
        __bfloat16_as_ushort(__float2bfloat16_rn(v.w - __bfloat162float(h3))));

    float ss = v.x * v.x + v.y * v.y + v.z * v.z + v.w * v.w;
    __shared__ float red[8];
#pragma unroll
    for (int o = 16; o; o >>= 1) ss += __shfl_xor_sync(~0u, ss, o);
    if ((t & 31) == 0) red[t >> 5] = ss;
    __syncthreads();
    if (t < 8) {
        float s = red[t];
#pragma unroll
        for (int o = 4; o; o >>= 1) s += __shfl_xor_sync(0xffu, s, o);
        if (t == 0) red[0] = s;
    }
    __syncthreads();
    float inv = 1.0f / fmaxf(sqrtf(red[0]), 1e-12f);
    ((ushort4*)(g_xnhi + (size_t)row * DM))[t] = make_ushort4(
        __bfloat16_as_ushort(__float2bfloat16_rn(v.x * inv)),
        __bfloat16_as_ushort(__float2bfloat16_rn(v.y * inv)),
        __bfloat16_as_ushort(__float2bfloat16_rn(v.z * inv)),
        __bfloat16_as_ushort(__float2bfloat16_rn(v.w * inv)));
}

// ---------------- 1b) weight hi/lo split ----------------
__global__ __launch_bounds__(256) void convw_kernel(const float* __restrict__ Wq,
        const float* __restrict__ Wk, const float* __restrict__ Wv) {
    int z = blockIdx.y;
    const float* W = (z == 0) ? Wq : (z == 1) ? Wk : Wv;
    size_t i = (size_t)blockIdx.x * 1024 + threadIdx.x * 4;
    float4 v = *(const float4*)(W + i);
    __nv_bfloat16 h0 = __float2bfloat16_rn(v.x), h1 = __float2bfloat16_rn(v.y);
    __nv_bfloat16 h2 = __float2bfloat16_rn(v.z), h3 = __float2bfloat16_rn(v.w);
    *(ushort4*)(g_whi[z] + i) = make_ushort4(
        __bfloat16_as_ushort(h0), __bfloat16_as_ushort(h1),
        __bfloat16_as_ushort(h2), __bfloat16_as_ushort(h3));
    *(ushort4*)(g_wlo[z] + i) = make_ushort4(
        __bfloat16_as_ushort(__float2bfloat16_rn(v.x - __bfloat162float(h0))),
        __bfloat16_as_ushort(__float2bfloat16_rn(v.y - __bfloat162float(h1))),
        __bfloat16_as_ushort(__float2bfloat16_rn(v.z - __bfloat162float(h2))),
        __bfloat16_as_ushort(__float2bfloat16_rn(v.w - __bfloat162float(h3))));
}

// ---------------- HMMA GEMM core: 128x128 CTA tile, BK=32, double-buffered --
// Both A and B are [rows][K=1024] bf16, K-contiguous. C = A * B^T.
// 8 warps: wm = wid&1 (m 0/64), wn = wid>>1 (n 0/32/64/96). Warp tile 64x32.
#define LDSR 40                 // padded smem row: 40 bf16 = 80 B
#define SBUF (128 * LDSR)       // one buffer: 5120 bf16

struct GSmem { __nv_bfloat16 A[2 * SBUF]; __nv_bfloat16 B[2 * SBUF]; };

__device__ __forceinline__ void g_load(const __nv_bfloat16* const* Aps,
                                       const __nv_bfloat16* const* Bps,
                                       uint32_t sA, uint32_t sB, int kt) {
    const int p = kt >> 5, kk = (kt & 31) * 32, buf = kt & 1;
    const __nv_bfloat16* Ag = Aps[p] + kk;
    const __nv_bfloat16* Bg = Bps[p] + kk;
#pragma unroll
    for (int h = 0; h < 2; h++) {
        int id = threadIdx.x + h * 256;     // 0..511
        int row = id >> 2, c8 = (id & 3) * 8;
        uint32_t so = (uint32_t)(buf * SBUF + row * LDSR + c8) * 2;
        CP_ASYNC16(sA + so, Ag + (size_t)row * DM + c8);
        CP_ASYNC16(sB + so, Bg + (size_t)row * DM + c8);
    }
}

__device__ __forceinline__ void g_compute(uint32_t sA, uint32_t sB, int buf,
                                          int wm, int wn, int lane,
                                          float acc[4][4][4]) {
#pragma unroll
    for (int ks = 0; ks < 2; ks++) {
        const int col = ks * 16 + (lane >> 4) * 8;
        uint32_t af[4][4], bf[2][4];
#pragma unroll
        for (int mt = 0; mt < 4; mt++) {
            int row = wm * 64 + mt * 16 + (lane & 15);
            ldsm4(af[mt], sA + (uint32_t)(buf * SBUF + row * LDSR + col) * 2);
        }
#pragma unroll
        for (int nt2 = 0; nt2 < 2; nt2++) {
            int row = wn * 32 + nt2 * 16 + (lane & 15);
            ldsm4(bf[nt2], sB + (uint32_t)(buf * SBUF + row * LDSR + col) * 2);
        }
#pragma unroll
        for (int mt = 0; mt < 4; mt++)
#pragma unroll
            for (int nt = 0; nt < 4; nt++) {
                uint32_t b0 = (nt & 1) ? bf[nt >> 1][1] : bf[nt >> 1][0];
                uint32_t b1 = (nt & 1) ? bf[nt >> 1][3] : bf[nt >> 1][2];
                mma16816(acc[mt][nt], af[mt], b0, b1);
            }
    }
}

__device__ __forceinline__ void g_mainloop(const __nv_bfloat16* const* Aps,
                                           const __nv_bfloat16* const* Bps,
                                           int npass, GSmem* sm,
                                           float acc[4][4][4]) {
    const uint32_t sA = smem_u32(sm->A), sB = smem_u32(sm->B);
    const int lane = threadIdx.x & 31, wid = threadIdx.x >> 5;
    const int wm = wid & 1, wn = wid >> 1;
#pragma unroll
    for (int mt = 0; mt < 4; mt++)
#pragma unroll
        for (int nt = 0; nt < 4; nt++)
#pragma unroll
            for (int r = 0; r < 4; r++) acc[mt][nt][r] = 0.f;

    const int KT = npass * 32;
    g_load(Aps, Bps, sA, sB, 0);
    CP_COMMIT();
    for (int kt = 0; kt < KT; kt++) {
        if (kt + 1 < KT) {
            g_load(Aps, Bps, sA, sB, kt + 1);
            CP_COMMIT();
            CP_WAIT1();
        } else {
            CP_WAIT0();
        }
        __syncthreads();
        g_compute(sA, sB, kt & 1, wm, wn, lane, acc);
        __syncthreads();
    }
}

// ---------------- 2) sim = xn @ xn^T -> threshold -> mask -------------------
__global__ __launch_bounds__(256, 2) void sim_kernel() {
    __shared__ GSmem sm;
    const int bz = blockIdx.z;
    const int m0 = blockIdx.y * 128, n0 = blockIdx.x * 128;
    const __nv_bfloat16* A = g_xnhi + ((size_t)bz * SEQ + m0) * DM;
    const __nv_bfloat16* B = g_xnhi + ((size_t)bz * SEQ + n0) * DM;
    const __nv_bfloat16* Aps[3] = {A, A, A};
    const __nv_bfloat16* Bps[3] = {B, B, B};
    float acc[4][4][4];
    g_mainloop(Aps, Bps, 1, &sm, acc);

    const int lane = threadIdx.x & 31, wid = threadIdx.x >> 5;
    const int wm = wid & 1, wn = wid >> 1;
    const int mb = m0 + wm * 64 + (lane >> 2);
    const int nb = n0 + wn * 32 + (lane & 3) * 2;
#pragma unroll
    for (int mt = 0; mt < 4; mt++)
#pragma unroll
        for (int rh = 0; rh < 2; rh++) {
            size_t ro = ((size_t)bz * SEQ + mb + mt * 16 + rh * 8) * SEQ;
#pragma unroll
            for (int nt = 0; nt < 4; nt++) {
                unsigned short u =
                    (acc[mt][nt][rh * 2 + 0] > 0.7f ? 1u : 0u) |
                    ((acc[mt][nt][rh * 2 + 1] > 0.7f ? 1u : 0u) << 8);
                *(unsigned short*)(g_mask + ro + nb + nt * 8) = u;
            }
        }
}

// ---------------- 3) projections: hi/lo 3-pass (K=3072) + bias --------------
__global__ __launch_bounds__(256, 2) void proj_kernel(const float* __restrict__ bq,
        const float* __restrict__ bk, const float* __restrict__ bv) {
    __shared__ GSmem sm;
    const int z = blockIdx.z;
    const int m0 = blockIdx.y * 128, n0 = blockIdx.x * 128;
    const float* bias = (z == 0) ? bq : (z == 1) ? bk : bv;
    float* Y = (z == 0) ? g_q : (z == 1) ? g_k : g_v;

    const __nv_bfloat16* Aps[3] = {g_xhi + (size_t)m0 * DM, g_xlo + (size_t)m0 * DM,
                                   g_xhi + (size_t)m0 * DM};
    const __nv_bfloat16* Bps[3] = {g_whi[z] + (size_t)n0 * DM, g_whi[z] + (size_t)n0 * DM,
                                   g_wlo[z] + (size_t)n0 * DM};
    float acc[4][4][4];
    g_mainloop(Aps, Bps, 3, &sm, acc);

    const int lane = threadIdx.x & 31, wid = threadIdx.x >> 5;
    const int wm = wid & 1, wn = wid >> 1;
    const int mb = m0 + wm * 64 + (lane >> 2);
    const int nb = n0 + wn * 32 + (lane & 3) * 2;
    float2 bv2[4];
#pragma unroll
    for (int nt = 0; nt < 4; nt++)
        bv2[nt] = make_float2(__ldg(bias + nb + nt * 8), __ldg(bias + nb + nt * 8 + 1));
#pragma unroll
    for (int mt = 0; mt < 4; mt++)
#pragma unroll
        for (int rh = 0; rh < 2; rh++) {
            float* yr = Y + (size_t)(mb + mt * 16 + rh * 8) * DM;
#pragma unroll
            for (int nt = 0; nt < 4; nt++) {
                float2 o = make_float2(acc[mt][nt][rh * 2 + 0] + bv2[nt].x,
                                       acc[mt][nt][rh * 2 + 1] + bv2[nt].y);
                *(float2*)(yr + nb + nt * 8) = o;
            }
        }
}

// ---------------- 2b) compact mask rows into index lists --------------------
__global__ __launch_bounds__(256) void build_idx_kernel() {
    int row = blockIdx.x * 8 + (threadIdx.x >> 5);
    int lane = threadIdx.x & 31;
    const unsigned* mrow = (const unsigned*)(g_mask + (size_t)row * SEQ);
    unsigned short* lst = g_idx + (size_t)row * SEQ;
    int count = 0;
#pragma unroll 4
    for (int it = 0; it < 16; ++it) {
        unsigned m4 = mrow[it * 32 + lane];
#pragma unroll
        for (int sub = 0; sub < 4; ++sub) {
            bool pred = ((m4 >> (8 * sub)) & 0xffu) != 0u;
            unsigned bal = __ballot_sync(~0u, pred);
            if (pred) {
                int pos = count + __popc(bal & ((1u << lane) - 1u));
                lst[pos] = (unsigned short)((it * 32 + lane) * 4 + sub);
            }
            count += __popc(bal);
        }
    }
    if (lane == 0) g_cnt[row] = count;
}

// ---------------- 4) sparse masked attention --------------------------------
__global__ __launch_bounds__(256) void attn_sparse_kernel(float* __restrict__ out) {
    __shared__ float qsm[8][64];
    const int w = threadIdx.x >> 5, lane = threadIdx.x & 31;
    const int gw = blockIdx.x * 8 + w;
    const int h = gw & (NH - 1);
    const int row = gw >> 4;
    const int b = row >> 11, s = row & (SEQ - 1);

    const int cnt = g_cnt[row];
    const unsigned short* lst = g_idx + (size_t)row * SEQ;
    float* ob = out + (((size_t)b * NH + h) * SEQ + s) * DK;
    const float* Vb = g_v + (size_t)b * SEQ * DM + h * DK;

    if (cnt == 1) {
        const float* vp = Vb + (size_t)lst[0] * DM;
        ob[lane]      = vp[lane];
        ob[lane + 32] = vp[lane + 32];
        return;
    }

    const float* Kb = g_k + (size_t)b * SEQ * DM + h * DK;
    const float* qp = g_q + ((size_t)b * SEQ + s) * DM + h * DK;
    float* qs = qsm[w];
    qs[lane] = qp[lane];
    qs[lane + 32] = qp[lane + 32];
    __syncwarp();

    float m = -1e30f, l = 0.f, o0 = 0.f, o1 = 0.f;
    for (int c0 = 0; c0 < cnt; c0 += 32) {
        int ci = c0 + lane;
        int tj = (ci < cnt) ? (int)lst[ci] : -1;
        float sc = -1e30f;
        if (tj >= 0) {
            const float* kp = Kb + (size_t)tj * DM;
            float a = 0.f;
#pragma unroll
            for (int d = 0; d < 64; d += 4) {
                float4 kq = *(const float4*)(kp + d);
                float4 qq = *(const float4*)(qs + d);
                a += kq.x * qq.x + kq.y * qq.y + kq.z * qq.z + kq.w * qq.w;
            }
            sc = a * 0.125f;
        }
        float mt = sc;
#pragma unroll
        for (int o = 16; o; o >>= 1) mt = fmaxf(mt, __shfl_xor_sync(~0u, mt, o));
        float mn = fmaxf(m, mt);
        float alpha = __expf(m - mn);
        float p = __expf(sc - mn);
        float ps = p;
#pragma unroll
        for (int o = 16; o; o >>= 1) ps += __shfl_xor_sync(~0u, ps, o);
        l = l * alpha + ps;
        o0 *= alpha; o1 *= alpha;
        m = mn;
        int nk = min(32, cnt - c0);
        for (int j = 0; j < nk; ++j) {
            float pj = __shfl_sync(~0u, p, j);
            int t = __shfl_sync(~0u, tj, j);
            const float* vp = Vb + (size_t)t * DM;
            o0 += pj * vp[lane];
            o1 += pj * vp[lane + 32];
        }
    }
    float invl = 1.0f / l;
    ob[lane]      = o0 * invl;
    ob[lane + 32] = o1 * invl;
}

// ---------------- launch ----------------------------------------------------
extern "C" void kernel_launch(void* const* d_in, const int* in_sizes, int n_in,
                              void* d_out, int out_size) {
    const float* x  = (const float*)d_in[0];
    const float* Wq = (const float*)d_in[1];
    const float* bq = (const float*)d_in[2];
    const float* Wk = (const float*)d_in[3];
    const float* bk = (const float*)d_in[4];
    const float* Wv = (const float*)d_in[5];
    const float* bv = (const float*)d_in[6];
    float* out = (float*)d_out;

    norm_kernel<<<BATCH * SEQ, 256>>>(x);
    convw_kernel<<<dim3(DM * DM / 1024, 3), 256>>>(Wq, Wk, Wv);
    sim_kernel<<<dim3(SEQ / 128, SEQ / 128, BATCH), 256>>>();
    build_idx_kernel<<<(BATCH * SEQ) / 8, 256>>>();
    proj_kernel<<<dim3(DM / 128, (BATCH * SEQ) / 128, 3), 256>>>(bq, bk, bv);
    attn_sparse_kernel<<<(BATCH * SEQ * NH) / 8, 256>>>(out);
}

// round 7
// speedup vs baseline: 9.5761x; 1.9391x over previous
#include <cuda_runtime.h>
#include <cuda_bf16.h>
#include <cstdint>

#define BATCH 2
#define SEQ   2048
#define DM    1024
#define NH    16
#define DK    64

// ---------------- scratch (allocation-free: device globals) ----------------
__device__ __nv_bfloat16 g_xnhi[BATCH * SEQ * DM];   // normalized x, bf16
__device__ __nv_bfloat16 g_xhi[BATCH * SEQ * DM];    // x hi
__device__ __nv_bfloat16 g_xlo[BATCH * SEQ * DM];    // x lo
__device__ __nv_bfloat16 g_whi[3][DM * DM];          // Wq/Wk/Wv hi
__device__ __nv_bfloat16 g_wvlo[DM * DM];            // Wv lo (only V needs hi/lo)
__device__ float g_q[BATCH * SEQ * DM];
__device__ float g_k[BATCH * SEQ * DM];
__device__ float g_v[BATCH * SEQ * DM];
__device__ unsigned char g_mask[BATCH * SEQ * SEQ];
__device__ unsigned short g_idx[(size_t)BATCH * SEQ * SEQ];
__device__ int g_cnt[BATCH * SEQ];

// ---------------- PTX helpers (sm_80-class: valid at base sm_103 target) ----
__device__ __forceinline__ uint32_t smem_u32(const void* p) {
    uint32_t a;
    asm("{ .reg .u64 t; cvta.to.shared.u64 t, %1; cvt.u32.u64 %0, t; }" : "=r"(a) : "l"(p));
    return a;
}
#define CP_ASYNC16(dst, src) \
    asm volatile("cp.async.cg.shared.global [%0], [%1], 16;" :: "r"(dst), "l"(src))
#define CP_COMMIT() asm volatile("cp.async.commit_group;" ::: "memory")
#define CP_WAIT1()  asm volatile("cp.async.wait_group 1;" ::: "memory")
#define CP_WAIT0()  asm volatile("cp.async.wait_group 0;" ::: "memory")

__device__ __forceinline__ void ldsm4(uint32_t* r, uint32_t addr) {
    asm volatile("ldmatrix.sync.aligned.m8n8.x4.shared.b16 {%0,%1,%2,%3}, [%4];"
                 : "=r"(r[0]), "=r"(r[1]), "=r"(r[2]), "=r"(r[3]) : "r"(addr));
}
__device__ __forceinline__ void mma16816(float* c, const uint32_t* a, uint32_t b0, uint32_t b1) {
    asm volatile("mma.sync.aligned.m16n8k16.row.col.f32.bf16.bf16.f32 "
                 "{%0,%1,%2,%3}, {%4,%5,%6,%7}, {%8,%9}, {%0,%1,%2,%3};"
                 : "+f"(c[0]), "+f"(c[1]), "+f"(c[2]), "+f"(c[3])
                 : "r"(a[0]), "r"(a[1]), "r"(a[2]), "r"(a[3]), "r"(b0), "r"(b1));
}

// ---------------- 1) norm + hi/lo split ----------------
__global__ __launch_bounds__(256) void norm_kernel(const float* __restrict__ x) {
    int row = blockIdx.x, t = threadIdx.x;
    float4 v = ((const float4*)(x + (size_t)row * DM))[t];

    __nv_bfloat16 h0 = __float2bfloat16_rn(v.x), h1 = __float2bfloat16_rn(v.y);
    __nv_bfloat16 h2 = __float2bfloat16_rn(v.z), h3 = __float2bfloat16_rn(v.w);
    ((ushort4*)(g_xhi + (size_t)row * DM))[t] = make_ushort4(
        __bfloat16_as_ushort(h0), __bfloat16_as_ushort(h1),
        __bfloat16_as_ushort(h2), __bfloat16_as_ushort(h3));
    ((ushort4*)(g_xlo + (size_t)row * DM))[t] = make_ushort4(
        __bfloat16_as_ushort(__float2bfloat16_rn(v.x - __bfloat162float(h0))),
        __bfloat16_as_ushort(__float2bfloat16_rn(v.y - __bfloat162float(h1))),
        __bfloat16_as_ushort(__float2bfloat16_rn(v.z - __bfloat162float(h2))),
        __bfloat16_as_ushort(__float2bfloat16_rn(v.w - __bfloat162float(h3))));

    float ss = v.x * v.x + v.y * v.y + v.z * v.z + v.w * v.w;
    __shared__ float red[8];
#pragma unroll
    for (int o = 16; o; o >>= 1) ss += __shfl_xor_sync(~0u, ss, o);
    if ((t & 31) == 0) red[t >> 5] = ss;
    __syncthreads();
    if (t < 8) {
        float s = red[t];
#pragma unroll
        for (int o = 4; o; o >>= 1) s += __shfl_xor_sync(0xffu, s, o);
        if (t == 0) red[0] = s;
    }
    __syncthreads();
    float inv = 1.0f / fmaxf(sqrtf(red[0]), 1e-12f);
    ((ushort4*)(g_xnhi + (size_t)row * DM))[t] = make_ushort4(
        __bfloat16_as_ushort(__float2bfloat16_rn(v.x * inv)),
        __bfloat16_as_ushort(__float2bfloat16_rn(v.y * inv)),
        __bfloat16_as_ushort(__float2bfloat16_rn(v.z * inv)),
        __bfloat16_as_ushort(__float2bfloat16_rn(v.w * inv)));
}

// ---------------- 1b) weight split: hi for all, lo only for V --------------
__global__ __launch_bounds__(256) void convw_kernel(const float* __restrict__ Wq,
        const float* __restrict__ Wk, const float* __restrict__ Wv) {
    int z = blockIdx.y;
    const float* W = (z == 0) ? Wq : (z == 1) ? Wk : Wv;
    size_t i = (size_t)blockIdx.x * 1024 + threadIdx.x * 4;
    float4 v = *(const float4*)(W + i);
    __nv_bfloat16 h0 = __float2bfloat16_rn(v.x), h1 = __float2bfloat16_rn(v.y);
    __nv_bfloat16 h2 = __float2bfloat16_rn(v.z), h3 = __float2bfloat16_rn(v.w);
    *(ushort4*)(g_whi[z] + i) = make_ushort4(
        __bfloat16_as_ushort(h0), __bfloat16_as_ushort(h1),
        __bfloat16_as_ushort(h2), __bfloat16_as_ushort(h3));
    if (z == 2) {
        *(ushort4*)(g_wvlo + i) = make_ushort4(
            __bfloat16_as_ushort(__float2bfloat16_rn(v.x - __bfloat162float(h0))),
            __bfloat16_as_ushort(__float2bfloat16_rn(v.y - __bfloat162float(h1))),
            __bfloat16_as_ushort(__float2bfloat16_rn(v.z - __bfloat162float(h2))),
            __bfloat16_as_ushort(__float2bfloat16_rn(v.w - __bfloat162float(h3))));
    }
}

// ---------------- HMMA GEMM core: 128x128 CTA tile, BK=32, 3-stage pipeline -
// Both A and B are [rows][K=1024] bf16, K-contiguous. C = A * B^T.
// 8 warps: wm = wid&1 (m 0/64), wn = wid>>1 (n 0/32/64/96). Warp tile 64x32.
#define LDSR 40                     // padded smem row: 40 bf16 = 80 B
#define SBUF (128 * LDSR)           // one stage: 5120 bf16
#define STAGES 3
#define GEMM_SMEM (STAGES * SBUF * 2 * 2)   // 61440 B

__device__ __forceinline__ void g_load(const __nv_bfloat16* const* Aps,
                                       const __nv_bfloat16* const* Bps,
                                       uint32_t sA, uint32_t sB, int kt, int stage) {
    const int p = kt >> 5, kk = (kt & 31) * 32;
    const __nv_bfloat16* Ag = Aps[p] + kk;
    const __nv_bfloat16* Bg = Bps[p] + kk;
#pragma unroll
    for (int h = 0; h < 2; h++) {
        int id = threadIdx.x + h * 256;     // 0..511
        int row = id >> 2, c8 = (id & 3) * 8;
        uint32_t so = (uint32_t)(stage * SBUF + row * LDSR + c8) * 2;
        CP_ASYNC16(sA + so, Ag + (size_t)row * DM + c8);
        CP_ASYNC16(sB + so, Bg + (size_t)row * DM + c8);
    }
}

__device__ __forceinline__ void g_compute(uint32_t sA, uint32_t sB, int stage,
                                          int wm, int wn, int lane,
                                          float acc[4][4][4]) {
#pragma unroll
    for (int ks = 0; ks < 2; ks++) {
        const int col = ks * 16 + (lane >> 4) * 8;
        uint32_t af[4][4], bf[2][4];
#pragma unroll
        for (int mt = 0; mt < 4; mt++) {
            int row = wm * 64 + mt * 16 + (lane & 15);
            ldsm4(af[mt], sA + (uint32_t)(stage * SBUF + row * LDSR + col) * 2);
        }
#pragma unroll
        for (int nt2 = 0; nt2 < 2; nt2++) {
            int row = wn * 32 + nt2 * 16 + (lane & 15);
            ldsm4(bf[nt2], sB + (uint32_t)(stage * SBUF + row * LDSR + col) * 2);
        }
#pragma unroll
        for (int mt = 0; mt < 4; mt++)
#pragma unroll
            for (int nt = 0; nt < 4; nt++) {
                uint32_t b0 = (nt & 1) ? bf[nt >> 1][1] : bf[nt >> 1][0];
                uint32_t b1 = (nt & 1) ? bf[nt >> 1][3] : bf[nt >> 1][2];
                mma16816(acc[mt][nt], af[mt], b0, b1);
            }
    }
}

__device__ __forceinline__ void g_mainloop(const __nv_bfloat16* const* Aps,
                                           const __nv_bfloat16* const* Bps,
                                           int npass, char* dyn,
                                           float acc[4][4][4]) {
    const uint32_t sA = smem_u32(dyn);
    const uint32_t sB = sA + STAGES * SBUF * 2;
    const int lane = threadIdx.x & 31, wid = threadIdx.x >> 5;
    const int wm = wid & 1, wn = wid >> 1;
#pragma unroll
    for (int mt = 0; mt < 4; mt++)
#pragma unroll
        for (int nt = 0; nt < 4; nt++)
#pragma unroll
            for (int r = 0; r < 4; r++) acc[mt][nt][r] = 0.f;

    const int KT = npass * 32;
    g_load(Aps, Bps, sA, sB, 0, 0); CP_COMMIT();
    g_load(Aps, Bps, sA, sB, 1, 1); CP_COMMIT();
    int st = 0, stp = 2;                      // compute stage, prefetch stage
    for (int kt = 0; kt < KT; kt++) {
        if (kt + 1 < KT) CP_WAIT1(); else CP_WAIT0();
        __syncthreads();
        g_compute(sA, sB, st, wm, wn, lane, acc);
        if (kt + 2 < KT) {
            g_load(Aps, Bps, sA, sB, kt + 2, stp);
            CP_COMMIT();
        }
        if (++st == STAGES) st = 0;
        if (++stp == STAGES) stp = 0;
    }
}

// ---------------- 2) sim = xn @ xn^T (upper-triangle tiles) -> mask ---------
// grid (136, BATCH): tile-pair (ti<=tj); mirror written via smem transpose.
__global__ __launch_bounds__(256, 2) void sim_kernel() {
    extern __shared__ char dyn[];
    const int bz = blockIdx.y;
    int t = blockIdx.x, ti = 0;
    while (t >= 16 - ti) { t -= 16 - ti; ti++; }
    const int tj = ti + t;
    const int m0 = ti * 128, n0 = tj * 128;
    const bool diag = (ti == tj);

    const __nv_bfloat16* A = g_xnhi + ((size_t)bz * SEQ + m0) * DM;
    const __nv_bfloat16* B = g_xnhi + ((size_t)bz * SEQ + n0) * DM;
    const __nv_bfloat16* Aps[1] = {A};
    const __nv_bfloat16* Bps[1] = {B};
    float acc[4][4][4];
    g_mainloop(Aps, Bps, 1, dyn, acc);
    __syncthreads();                          // smem reuse barrier

    unsigned char* T  = (unsigned char*)dyn;          // [128][132]
    unsigned char* TT = T + 128 * 132;                // [128][132] transposed
    const int lane = threadIdx.x & 31, wid = threadIdx.x >> 5;
    const int wm = wid & 1, wn = wid >> 1;
#pragma unroll
    for (int mt = 0; mt < 4; mt++)
#pragma unroll
        for (int nt = 0; nt < 4; nt++)
#pragma unroll
            for (int rh = 0; rh < 2; rh++)
#pragma unroll
                for (int e = 0; e < 2; e++) {
                    int row = wm * 64 + mt * 16 + rh * 8 + (lane >> 2);
                    int col = wn * 32 + nt * 8 + (lane & 3) * 2 + e;
                    unsigned char bit = acc[mt][nt][rh * 2 + e] > 0.7f ? 1 : 0;
                    T[row * 132 + col] = bit;
                    if (!diag) TT[col * 132 + row] = bit;
                }
    __syncthreads();
#pragma unroll
    for (int i = 0; i < 16; i++) {
        int idx = threadIdx.x + i * 256;
        int row = idx >> 5, c4 = (idx & 31) * 4;
        uint32_t w = *(uint32_t*)(T + row * 132 + c4);
        *(uint32_t*)(g_mask + ((size_t)bz * SEQ + m0 + row) * SEQ + n0 + c4) = w;
    }
    if (!diag) {
#pragma unroll
        for (int i = 0; i < 16; i++) {
            int idx = threadIdx.x + i * 256;
            int row = idx >> 5, c4 = (idx & 31) * 4;
            uint32_t w = *(uint32_t*)(TT + row * 132 + c4);
            *(uint32_t*)(g_mask + ((size_t)bz * SEQ + n0 + row) * SEQ + m0 + c4) = w;
        }
    }
}

// ---------------- 3) projections: V = 3-pass hi/lo, Q/K = 1 bf16 pass -------
// z order: 0 -> V (heavy, launches first), 1 -> Q, 2 -> K
__global__ __launch_bounds__(256, 2) void proj_kernel(const float* __restrict__ bq,
        const float* __restrict__ bk, const float* __restrict__ bv) {
    extern __shared__ char dyn[];
    const int sel = blockIdx.z;               // 0=V, 1=Q, 2=K
    const int m0 = blockIdx.y * 128, n0 = blockIdx.x * 128;
    const float* bias = (sel == 0) ? bv : (sel == 1) ? bq : bk;
    float* Y = (sel == 0) ? g_v : (sel == 1) ? g_q : g_k;
    const int wz = (sel == 0) ? 2 : (sel == 1) ? 0 : 1;
    const int npass = (sel == 0) ? 3 : 1;

    const __nv_bfloat16* Aps[3] = {g_xhi + (size_t)m0 * DM, g_xlo + (size_t)m0 * DM,
                                   g_xhi + (size_t)m0 * DM};
    const __nv_bfloat16* Bps[3] = {g_whi[wz] + (size_t)n0 * DM, g_whi[wz] + (size_t)n0 * DM,
                                   g_wvlo + (size_t)n0 * DM};
    float acc[4][4][4];
    g_mainloop(Aps, Bps, npass, dyn, acc);

    const int lane = threadIdx.x & 31, wid = threadIdx.x >> 5;
    const int wm = wid & 1, wn = wid >> 1;
    const int mb = m0 + wm * 64 + (lane >> 2);
    const int nb = n0 + wn * 32 + (lane & 3) * 2;
    float2 bv2[4];
#pragma unroll
    for (int nt = 0; nt < 4; nt++)
        bv2[nt] = make_float2(__ldg(bias + nb + nt * 8), __ldg(bias + nb + nt * 8 + 1));
#pragma unroll
    for (int mt = 0; mt < 4; mt++)
#pragma unroll
        for (int rh = 0; rh < 2; rh++) {
            float* yr = Y + (size_t)(mb + mt * 16 + rh * 8) * DM;
#pragma unroll
            for (int nt = 0; nt < 4; nt++) {
                float2 o = make_float2(acc[mt][nt][rh * 2 + 0] + bv2[nt].x,
                                       acc[mt][nt][rh * 2 + 1] + bv2[nt].y);
                *(float2*)(yr + nb + nt * 8) = o;
            }
        }
}

// ---------------- 2b) compact mask rows into index lists --------------------
__global__ __launch_bounds__(256) void build_idx_kernel() {
    int row = blockIdx.x * 8 + (threadIdx.x >> 5);
    int lane = threadIdx.x & 31;
    const unsigned* mrow = (const unsigned*)(g_mask + (size_t)row * SEQ);
    unsigned short* lst = g_idx + (size_t)row * SEQ;
    int count = 0;
#pragma unroll 4
    for (int it = 0; it < 16; ++it) {
        unsigned m4 = mrow[it * 32 + lane];
#pragma unroll
        for (int sub = 0; sub < 4; ++sub) {
            bool pred = ((m4 >> (8 * sub)) & 0xffu) != 0u;
            unsigned bal = __ballot_sync(~0u, pred);
            if (pred) {
                int pos = count + __popc(bal & ((1u << lane) - 1u));
                lst[pos] = (unsigned short)((it * 32 + lane) * 4 + sub);
            }
            count += __popc(bal);
        }
    }
    if (lane == 0) g_cnt[row] = count;
}

// ---------------- 4) sparse masked attention --------------------------------
__global__ __launch_bounds__(256) void attn_sparse_kernel(float* __restrict__ out) {
    __shared__ float qsm[8][64];
    const int w = threadIdx.x >> 5, lane = threadIdx.x & 31;
    const int gw = blockIdx.x * 8 + w;
    const int h = gw & (NH - 1);
    const int row = gw >> 4;
    const int b = row >> 11, s = row & (SEQ - 1);

    const int cnt = g_cnt[row];
    const unsigned short* lst = g_idx + (size_t)row * SEQ;
    float* ob = out + (((size_t)b * NH + h) * SEQ + s) * DK;
    const float* Vb = g_v + (size_t)b * SEQ * DM + h * DK;

    if (cnt == 1) {
        const float* vp = Vb + (size_t)lst[0] * DM;
        ob[lane]      = vp[lane];
        ob[lane + 32] = vp[lane + 32];
        return;
    }

    const float* Kb = g_k + (size_t)b * SEQ * DM + h * DK;
    const float* qp = g_q + ((size_t)b * SEQ + s) * DM + h * DK;
    float* qs = qsm[w];
    qs[lane] = qp[lane];
    qs[lane + 32] = qp[lane + 32];
    __syncwarp();

    float m = -1e30f, l = 0.f, o0 = 0.f, o1 = 0.f;
    for (int c0 = 0; c0 < cnt; c0 += 32) {
        int ci = c0 + lane;
        int tj = (ci < cnt) ? (int)lst[ci] : -1;
        float sc = -1e30f;
        if (tj >= 0) {
            const float* kp = Kb + (size_t)tj * DM;
            float a = 0.f;
#pragma unroll
            for (int d = 0; d < 64; d += 4) {
                float4 kq = *(const float4*)(kp + d);
                float4 qq = *(const float4*)(qs + d);
                a += kq.x * qq.x + kq.y * qq.y + kq.z * qq.z + kq.w * qq.w;
            }
            sc = a * 0.125f;
        }
        float mt = sc;
#pragma unroll
        for (int o = 16; o; o >>= 1) mt = fmaxf(mt, __shfl_xor_sync(~0u, mt, o));
        float mn = fmaxf(m, mt);
        float alpha = __expf(m - mn);
        float p = __expf(sc - mn);
        float ps = p;
#pragma unroll
        for (int o = 16; o; o >>= 1) ps += __shfl_xor_sync(~0u, ps, o);
        l = l * alpha + ps;
        o0 *= alpha; o1 *= alpha;
        m = mn;
        int nk = min(32, cnt - c0);
        for (int j = 0; j < nk; ++j) {
            float pj = __shfl_sync(~0u, p, j);
            int t = __shfl_sync(~0u, tj, j);
            const float* vp = Vb + (size_t)t * DM;
            o0 += pj * vp[lane];
            o1 += pj * vp[lane + 32];
        }
    }
    float invl = 1.0f / l;
    ob[lane]      = o0 * invl;
    ob[lane + 32] = o1 * invl;
}

// ---------------- launch ----------------------------------------------------
extern "C" void kernel_launch(void* const* d_in, const int* in_sizes, int n_in,
                              void* d_out, int out_size) {
    const float* x  = (const float*)d_in[0];
    const float* Wq = (const float*)d_in[1];
    const float* bq = (const float*)d_in[2];
    const float* Wk = (const float*)d_in[3];
    const float* bk = (const float*)d_in[4];
    const float* Wv = (const float*)d_in[5];
    const float* bv = (const float*)d_in[6];
    float* out = (float*)d_out;

    cudaFuncSetAttribute(sim_kernel, cudaFuncAttributeMaxDynamicSharedMemorySize, GEMM_SMEM);
    cudaFuncSetAttribute(proj_kernel, cudaFuncAttributeMaxDynamicSharedMemorySize, GEMM_SMEM);

    norm_kernel<<<BATCH * SEQ, 256>>>(x);
    convw_kernel<<<dim3(DM * DM / 1024, 3), 256>>>(Wq, Wk, Wv);
    sim_kernel<<<dim3(136, BATCH), 256, GEMM_SMEM>>>();
    build_idx_kernel<<<(BATCH * SEQ) / 8, 256>>>();
    proj_kernel<<<dim3(DM / 128, (BATCH * SEQ) / 128, 3), 256, GEMM_SMEM>>>(bq, bk, bv);
    attn_sparse_kernel<<<(BATCH * SEQ * NH) / 8, 256>>>(out);
}

// round 8
// speedup vs baseline: 12.6410x; 1.3201x over previous
#include <cuda_runtime.h>
#include <cuda_bf16.h>
#include <cstdint>

#define BATCH 2
#define SEQ   2048
#define DM    1024
#define NH    16
#define DK    64

// ---------------- scratch (allocation-free: device globals) ----------------
__device__ __nv_bfloat16 g_xnhi[BATCH * SEQ * DM];   // normalized x, bf16
__device__ __nv_bfloat16 g_xhi[BATCH * SEQ * DM];    // x hi
__device__ __nv_bfloat16 g_xlo[BATCH * SEQ * DM];    // x lo
__device__ __nv_bfloat16 g_wvhi[DM * DM];            // Wv hi
__device__ __nv_bfloat16 g_wvlo[DM * DM];            // Wv lo
__device__ float g_v[BATCH * SEQ * DM];
__device__ unsigned short g_idx[(size_t)BATCH * SEQ * SEQ];
__device__ int g_cnt[BATCH * SEQ];

// ---------------- PTX helpers (sm_80-class: valid at base sm_103 target) ----
__device__ __forceinline__ uint32_t smem_u32(const void* p) {
    uint32_t a;
    asm("{ .reg .u64 t; cvta.to.shared.u64 t, %1; cvt.u32.u64 %0, t; }" : "=r"(a) : "l"(p));
    return a;
}
#define CP_ASYNC16(dst, src) \
    asm volatile("cp.async.cg.shared.global [%0], [%1], 16;" :: "r"(dst), "l"(src))
#define CP_COMMIT() asm volatile("cp.async.commit_group;" ::: "memory")
#define CP_WAIT1()  asm volatile("cp.async.wait_group 1;" ::: "memory")
#define CP_WAIT0()  asm volatile("cp.async.wait_group 0;" ::: "memory")

__device__ __forceinline__ void ldsm4(uint32_t* r, uint32_t addr) {
    asm volatile("ldmatrix.sync.aligned.m8n8.x4.shared.b16 {%0,%1,%2,%3}, [%4];"
                 : "=r"(r[0]), "=r"(r[1]), "=r"(r[2]), "=r"(r[3]) : "r"(addr));
}
__device__ __forceinline__ void mma16816(float* c, const uint32_t* a, uint32_t b0, uint32_t b1) {
    asm volatile("mma.sync.aligned.m16n8k16.row.col.f32.bf16.bf16.f32 "
                 "{%0,%1,%2,%3}, {%4,%5,%6,%7}, {%8,%9}, {%0,%1,%2,%3};"
                 : "+f"(c[0]), "+f"(c[1]), "+f"(c[2]), "+f"(c[3])
                 : "r"(a[0]), "r"(a[1]), "r"(a[2]), "r"(a[3]), "r"(b0), "r"(b1));
}

// ---------------- 1) norm + hi/lo split (+ zero g_cnt) ----------------
__global__ __launch_bounds__(256) void norm_kernel(const float* __restrict__ x) {
    int row = blockIdx.x, t = threadIdx.x;
    if (t == 0) g_cnt[row] = 0;
    float4 v = ((const float4*)(x + (size_t)row * DM))[t];

    __nv_bfloat16 h0 = __float2bfloat16_rn(v.x), h1 = __float2bfloat16_rn(v.y);
    __nv_bfloat16 h2 = __float2bfloat16_rn(v.z), h3 = __float2bfloat16_rn(v.w);
    ((ushort4*)(g_xhi + (size_t)row * DM))[t] = make_ushort4(
        __bfloat16_as_ushort(h0), __bfloat16_as_ushort(h1),
        __bfloat16_as_ushort(h2), __bfloat16_as_ushort(h3));
    ((ushort4*)(g_xlo + (size_t)row * DM))[t] = make_ushort4(
        __bfloat16_as_ushort(__float2bfloat16_rn(v.x - __bfloat162float(h0))),
        __bfloat16_as_ushort(__float2bfloat16_rn(v.y - __bfloat162float(h1))),
        __bfloat16_as_ushort(__float2bfloat16_rn(v.z - __bfloat162float(h2))),
        __bfloat16_as_ushort(__float2bfloat16_rn(v.w - __bfloat162float(h3))));

    float ss = v.x * v.x + v.y * v.y + v.z * v.z + v.w * v.w;
    __shared__ float red[8];
#pragma unroll
    for (int o = 16; o; o >>= 1) ss += __shfl_xor_sync(~0u, ss, o);
    if ((t & 31) == 0) red[t >> 5] = ss;
    __syncthreads();
    if (t < 8) {
        float s = red[t];
#pragma unroll
        for (int o = 4; o; o >>= 1) s += __shfl_xor_sync(0xffu, s, o);
        if (t == 0) red[0] = s;
    }
    __syncthreads();
    float inv = 1.0f / fmaxf(sqrtf(red[0]), 1e-12f);
    ((ushort4*)(g_xnhi + (size_t)row * DM))[t] = make_ushort4(
        __bfloat16_as_ushort(__float2bfloat16_rn(v.x * inv)),
        __bfloat16_as_ushort(__float2bfloat16_rn(v.y * inv)),
        __bfloat16_as_ushort(__float2bfloat16_rn(v.z * inv)),
        __bfloat16_as_ushort(__float2bfloat16_rn(v.w * inv)));
}

// ---------------- 1b) Wv hi/lo split ----------------
__global__ __launch_bounds__(256) void convw_kernel(const float* __restrict__ Wv) {
    size_t i = (size_t)blockIdx.x * 1024 + threadIdx.x * 4;
    float4 v = *(const float4*)(Wv + i);
    __nv_bfloat16 h0 = __float2bfloat16_rn(v.x), h1 = __float2bfloat16_rn(v.y);
    __nv_bfloat16 h2 = __float2bfloat16_rn(v.z), h3 = __float2bfloat16_rn(v.w);
    *(ushort4*)(g_wvhi + i) = make_ushort4(
        __bfloat16_as_ushort(h0), __bfloat16_as_ushort(h1),
        __bfloat16_as_ushort(h2), __bfloat16_as_ushort(h3));
    *(ushort4*)(g_wvlo + i) = make_ushort4(
        __bfloat16_as_ushort(__float2bfloat16_rn(v.x - __bfloat162float(h0))),
        __bfloat16_as_ushort(__float2bfloat16_rn(v.y - __bfloat162float(h1))),
        __bfloat16_as_ushort(__float2bfloat16_rn(v.z - __bfloat162float(h2))),
        __bfloat16_as_ushort(__float2bfloat16_rn(v.w - __bfloat162float(h3))));
}

// ---------------- HMMA GEMM core: 128x128 CTA tile, BK=32, 3-stage pipeline -
#define LDSR 40                     // padded smem row: 40 bf16 = 80 B
#define SBUF (128 * LDSR)           // one stage: 5120 bf16
#define STAGES 3
#define GEMM_SMEM (STAGES * SBUF * 2 * 2)   // 61440 B

__device__ __forceinline__ void g_load(const __nv_bfloat16* const* Aps,
                                       const __nv_bfloat16* const* Bps,
                                       uint32_t sA, uint32_t sB, int kt, int stage) {
    const int p = kt >> 5, kk = (kt & 31) * 32;
    const __nv_bfloat16* Ag = Aps[p] + kk;
    const __nv_bfloat16* Bg = Bps[p] + kk;
#pragma unroll
    for (int h = 0; h < 2; h++) {
        int id = threadIdx.x + h * 256;     // 0..511
        int row = id >> 2, c8 = (id & 3) * 8;
        uint32_t so = (uint32_t)(stage * SBUF + row * LDSR + c8) * 2;
        CP_ASYNC16(sA + so, Ag + (size_t)row * DM + c8);
        CP_ASYNC16(sB + so, Bg + (size_t)row * DM + c8);
    }
}

__device__ __forceinline__ void g_compute(uint32_t sA, uint32_t sB, int stage,
                                          int wm, int wn, int lane,
                                          float acc[4][4][4]) {
#pragma unroll
    for (int ks = 0; ks < 2; ks++) {
        const int col = ks * 16 + (lane >> 4) * 8;
        uint32_t af[4][4], bf[2][4];
#pragma unroll
        for (int mt = 0; mt < 4; mt++) {
            int row = wm * 64 + mt * 16 + (lane & 15);
            ldsm4(af[mt], sA + (uint32_t)(stage * SBUF + row * LDSR + col) * 2);
        }
#pragma unroll
        for (int nt2 = 0; nt2 < 2; nt2++) {
            int row = wn * 32 + nt2 * 16 + (lane & 15);
            ldsm4(bf[nt2], sB + (uint32_t)(stage * SBUF + row * LDSR + col) * 2);
        }
#pragma unroll
        for (int mt = 0; mt < 4; mt++)
#pragma unroll
            for (int nt = 0; nt < 4; nt++) {
                uint32_t b0 = (nt & 1) ? bf[nt >> 1][1] : bf[nt >> 1][0];
                uint32_t b1 = (nt & 1) ? bf[nt >> 1][3] : bf[nt >> 1][2];
                mma16816(acc[mt][nt], af[mt], b0, b1);
            }
    }
}

__device__ __forceinline__ void g_mainloop(const __nv_bfloat16* const* Aps,
                                           const __nv_bfloat16* const* Bps,
                                           int npass, char* dyn,
                                           float acc[4][4][4]) {
    const uint32_t sA = smem_u32(dyn);
    const uint32_t sB = sA + STAGES * SBUF * 2;
    const int lane = threadIdx.x & 31, wid = threadIdx.x >> 5;
    const int wm = wid & 1, wn = wid >> 1;
#pragma unroll
    for (int mt = 0; mt < 4; mt++)
#pragma unroll
        for (int nt = 0; nt < 4; nt++)
#pragma unroll
            for (int r = 0; r < 4; r++) acc[mt][nt][r] = 0.f;

    const int KT = npass * 32;
    g_load(Aps, Bps, sA, sB, 0, 0); CP_COMMIT();
    g_load(Aps, Bps, sA, sB, 1, 1); CP_COMMIT();
    int st = 0, stp = 2;                      // compute stage, prefetch stage
    for (int kt = 0; kt < KT; kt++) {
        if (kt + 1 < KT) CP_WAIT1(); else CP_WAIT0();
        __syncthreads();
        g_compute(sA, sB, st, wm, wn, lane, acc);
        if (kt + 2 < KT) {
            g_load(Aps, Bps, sA, sB, kt + 2, stp);
            CP_COMMIT();
        }
        if (++st == STAGES) st = 0;
        if (++stp == STAGES) stp = 0;
    }
}

// ---------------- 2) sim (upper-triangle tiles) -> compact idx lists --------
// grid (136, BATCH). Survivors are compacted straight into g_idx/g_cnt.
__global__ __launch_bounds__(256, 2) void sim_kernel() {
    extern __shared__ char dyn[];
    const int bz = blockIdx.y;
    int t = blockIdx.x, ti = 0;
    while (t >= 16 - ti) { t -= 16 - ti; ti++; }
    const int tj = ti + t;
    const int m0 = ti * 128, n0 = tj * 128;
    const bool diag = (ti == tj);

    const __nv_bfloat16* A = g_xnhi + ((size_t)bz * SEQ + m0) * DM;
    const __nv_bfloat16* B = g_xnhi + ((size_t)bz * SEQ + n0) * DM;
    const __nv_bfloat16* Aps[1] = {A};
    const __nv_bfloat16* Bps[1] = {B};
    float acc[4][4][4];
    g_mainloop(Aps, Bps, 1, dyn, acc);
    __syncthreads();                          // smem reuse barrier

    unsigned char* T  = (unsigned char*)dyn;          // [128][132]
    unsigned char* TT = T + 128 * 132;                // transposed copy
    const int lane = threadIdx.x & 31, wid = threadIdx.x >> 5;
    const int wm = wid & 1, wn = wid >> 1;
#pragma unroll
    for (int mt = 0; mt < 4; mt++)
#pragma unroll
        for (int nt = 0; nt < 4; nt++)
#pragma unroll
            for (int rh = 0; rh < 2; rh++)
#pragma unroll
                for (int e = 0; e < 2; e++) {
                    int row = wm * 64 + mt * 16 + rh * 8 + (lane >> 2);
                    int col = wn * 32 + nt * 8 + (lane & 3) * 2 + e;
                    unsigned char bit = acc[mt][nt][rh * 2 + e] > 0.7f ? 1 : 0;
                    T[row * 132 + col] = bit;
                    if (!diag) TT[col * 132 + row] = bit;
                }
    __syncthreads();

    // ballot-compact rows of T (and TT for the mirror) into g_idx
    const int nview = diag ? 1 : 2;
    for (int vw = 0; vw < nview; vw++) {
        const unsigned char* M = vw ? TT : T;
        const int r0 = vw ? n0 : m0;          // global row base
        const int c0 = vw ? m0 : n0;          // global col base
#pragma unroll 2
        for (int r = 0; r < 16; r++) {
            int row = wid * 16 + r;
            unsigned m4 = *(const unsigned*)(M + row * 132 + lane * 4);
            int grow = bz * SEQ + r0 + row;
            int total = 0;
            unsigned bal[4];
            int pos[4];
#pragma unroll
            for (int sub = 0; sub < 4; sub++) {
                bool pred = ((m4 >> (8 * sub)) & 0xffu) != 0u;
                bal[sub] = __ballot_sync(~0u, pred);
                pos[sub] = total + __popc(bal[sub] & ((1u << lane) - 1u));
                total += __popc(bal[sub]);
            }
            if (total > 0) {
                int base = 0;
                if (lane == 0) base = atomicAdd(&g_cnt[grow], total);
                base = __shfl_sync(~0u, base, 0);
                unsigned short* lst = g_idx + (size_t)grow * SEQ + base;
#pragma unroll
                for (int sub = 0; sub < 4; sub++)
                    if ((bal[sub] >> lane) & 1u)
                        lst[pos[sub]] = (unsigned short)(c0 + lane * 4 + sub);
            }
        }
    }
}

// ---------------- 3) V projection: hi/lo 3-pass + bias ----------------------
__global__ __launch_bounds__(256, 2) void proj_kernel(const float* __restrict__ bv) {
    extern __shared__ char dyn[];
    const int m0 = blockIdx.y * 128, n0 = blockIdx.x * 128;

    const __nv_bfloat16* Aps[3] = {g_xhi + (size_t)m0 * DM, g_xlo + (size_t)m0 * DM,
                                   g_xhi + (size_t)m0 * DM};
    const __nv_bfloat16* Bps[3] = {g_wvhi + (size_t)n0 * DM, g_wvhi + (size_t)n0 * DM,
                                   g_wvlo + (size_t)n0 * DM};
    float acc[4][4][4];
    g_mainloop(Aps, Bps, 3, dyn, acc);

    const int lane = threadIdx.x & 31, wid = threadIdx.x >> 5;
    const int wm = wid & 1, wn = wid >> 1;
    const int mb = m0 + wm * 64 + (lane >> 2);
    const int nb = n0 + wn * 32 + (lane & 3) * 2;
    float2 bv2[4];
#pragma unroll
    for (int nt = 0; nt < 4; nt++)
        bv2[nt] = make_float2(__ldg(bv + nb + nt * 8), __ldg(bv + nb + nt * 8 + 1));
#pragma unroll
    for (int mt = 0; mt < 4; mt++)
#pragma unroll
        for (int rh = 0; rh < 2; rh++) {
            float* yr = g_v + (size_t)(mb + mt * 16 + rh * 8) * DM;
#pragma unroll
            for (int nt = 0; nt < 4; nt++) {
                float2 o = make_float2(acc[mt][nt][rh * 2 + 0] + bv2[nt].x,
                                       acc[mt][nt][rh * 2 + 1] + bv2[nt].y);
                *(float2*)(yr + nb + nt * 8) = o;
            }
        }
}

// ---------------- helper: on-the-fly fp32 projection of one head row --------
// lane holds outputs d=lane and d=lane+32 of head h for input row xr.
__device__ __forceinline__ void proj_row_head(const float* __restrict__ xr,
                                              const float* __restrict__ W,
                                              const float* __restrict__ bias,
                                              int h, int lane,
                                              float& r0, float& r1) {
    const float* w0 = W + (size_t)(h * DK + lane) * DM;
    const float* w1 = W + (size_t)(h * DK + lane + 32) * DM;
    r0 = bias[h * DK + lane];
    r1 = bias[h * DK + lane + 32];
    for (int k0 = 0; k0 < DM; k0 += 32) {
        float xv = xr[k0 + lane];
#pragma unroll
        for (int j = 0; j < 32; j++) {
            float xj = __shfl_sync(~0u, xv, j);
            r0 = fmaf(w0[k0 + j], xj, r0);
            r1 = fmaf(w1[k0 + j], xj, r1);
        }
    }
}

// ---------------- 4) sparse masked attention --------------------------------
// warp per (row, head). cnt==1: output = gathered v row (softmax weight = 1).
// cnt>1 (rare): q and each needed k computed on the fly in fp32.
__global__ __launch_bounds__(256) void attn_sparse_kernel(
        const float* __restrict__ x,
        const float* __restrict__ Wq, const float* __restrict__ bq,
        const float* __restrict__ Wk, const float* __restrict__ bk,
        float* __restrict__ out) {
    const int w = threadIdx.x >> 5, lane = threadIdx.x & 31;
    const int gw = blockIdx.x * 8 + w;
    const int h = gw & (NH - 1);
    const int row = gw >> 4;
    const int b = row >> 11, s = row & (SEQ - 1);

    const int cnt = g_cnt[row];
    const unsigned short* lst = g_idx + (size_t)row * SEQ;
    float* ob = out + (((size_t)b * NH + h) * SEQ + s) * DK;
    const float* Vb = g_v + (size_t)b * SEQ * DM + h * DK;

    if (cnt == 1) {
        const float* vp = Vb + (size_t)lst[0] * DM;
        ob[lane]      = vp[lane];
        ob[lane + 32] = vp[lane + 32];
        return;
    }

    // slow path: fp32 on-the-fly q/k
    const float* xb = x + (size_t)b * SEQ * DM;
    float q0, q1;
    proj_row_head(xb + (size_t)s * DM, Wq, bq, h, lane, q0, q1);

    float m = -1e30f, l = 0.f, o0 = 0.f, o1 = 0.f;
    for (int ci = 0; ci < cnt; ci++) {
        int tj = (int)lst[ci];
        float k0, k1;
        proj_row_head(xb + (size_t)tj * DM, Wk, bk, h, lane, k0, k1);
        float part = q0 * k0 + q1 * k1;
#pragma unroll
        for (int o = 16; o; o >>= 1) part += __shfl_xor_sync(~0u, part, o);
        float sc = part * 0.125f;             // 1/sqrt(64)
        float mn = fmaxf(m, sc);
        float alpha = __expf(m - mn);
        float p = __expf(sc - mn);
        l = l * alpha + p;
        const float* vp = Vb + (size_t)tj * DM;
        o0 = o0 * alpha + p * vp[lane];
        o1 = o1 * alpha + p * vp[lane + 32];
        m = mn;
    }
    float invl = 1.0f / l;
    ob[lane]      = o0 * invl;
    ob[lane + 32] = o1 * invl;
}

// ---------------- launch ----------------------------------------------------
extern "C" void kernel_launch(void* const* d_in, const int* in_sizes, int n_in,
                              void* d_out, int out_size) {
    const float* x  = (const float*)d_in[0];
    const float* Wq = (const float*)d_in[1];
    const float* bq = (const float*)d_in[2];
    const float* Wk = (const float*)d_in[3];
    const float* bk = (const float*)d_in[4];
    const float* Wv = (const float*)d_in[5];
    const float* bv = (const float*)d_in[6];
    float* out = (float*)d_out;

    cudaFuncSetAttribute(sim_kernel, cudaFuncAttributeMaxDynamicSharedMemorySize, GEMM_SMEM);
    cudaFuncSetAttribute(proj_kernel, cudaFuncAttributeMaxDynamicSharedMemorySize, GEMM_SMEM);

    norm_kernel<<<BATCH * SEQ, 256>>>(x);
    convw_kernel<<<DM * DM / 1024, 256>>>(Wv);
    sim_kernel<<<dim3(136, BATCH), 256, GEMM_SMEM>>>();
    proj_kernel<<<dim3(DM / 128, (BATCH * SEQ) / 128), 256, GEMM_SMEM>>>(bv);
    attn_sparse_kernel<<<(BATCH * SEQ * NH) / 8, 256>>>(x, Wq, bq, Wk, bk, out);
}

// round 9
// speedup vs baseline: 21.3835x; 1.6916x over previous
#include <cuda_runtime.h>
#include <cuda_bf16.h>
#include <cuda_fp16.h>
#include <cstdint>

#define BATCH 2
#define SEQ   2048
#define DM    1024
#define NH    16
#define DK    64

// ---------------- scratch (allocation-free: device globals) ----------------
__device__ __nv_bfloat16 g_xnhi[BATCH * SEQ * DM];   // normalized x, bf16 (sim)
__device__ __half g_xh[BATCH * SEQ * DM];            // x fp16 (V proj)
__device__ __half g_wvh[DM * DM];                    // Wv fp16
__device__ float g_v[BATCH * SEQ * DM];
__device__ unsigned short g_idx[(size_t)BATCH * SEQ * SEQ];
__device__ int g_cnt[BATCH * SEQ];

// ---------------- PTX helpers (sm_80-class: valid at base sm_103 target) ----
__device__ __forceinline__ uint32_t smem_u32(const void* p) {
    uint32_t a;
    asm("{ .reg .u64 t; cvta.to.shared.u64 t, %1; cvt.u32.u64 %0, t; }" : "=r"(a) : "l"(p));
    return a;
}
#define CP_ASYNC16(dst, src) \
    asm volatile("cp.async.cg.shared.global [%0], [%1], 16;" :: "r"(dst), "l"(src))
#define CP_COMMIT() asm volatile("cp.async.commit_group;" ::: "memory")
#define CP_WAIT1()  asm volatile("cp.async.wait_group 1;" ::: "memory")
#define CP_WAIT0()  asm volatile("cp.async.wait_group 0;" ::: "memory")

__device__ __forceinline__ void ldsm4(uint32_t* r, uint32_t addr) {
    asm volatile("ldmatrix.sync.aligned.m8n8.x4.shared.b16 {%0,%1,%2,%3}, [%4];"
                 : "=r"(r[0]), "=r"(r[1]), "=r"(r[2]), "=r"(r[3]) : "r"(addr));
}
template <bool F16>
__device__ __forceinline__ void mma16816(float* c, const uint32_t* a, uint32_t b0, uint32_t b1) {
    if (F16)
        asm volatile("mma.sync.aligned.m16n8k16.row.col.f32.f16.f16.f32 "
                     "{%0,%1,%2,%3}, {%4,%5,%6,%7}, {%8,%9}, {%0,%1,%2,%3};"
                     : "+f"(c[0]), "+f"(c[1]), "+f"(c[2]), "+f"(c[3])
                     : "r"(a[0]), "r"(a[1]), "r"(a[2]), "r"(a[3]), "r"(b0), "r"(b1));
    else
        asm volatile("mma.sync.aligned.m16n8k16.row.col.f32.bf16.bf16.f32 "
                     "{%0,%1,%2,%3}, {%4,%5,%6,%7}, {%8,%9}, {%0,%1,%2,%3};"
                     : "+f"(c[0]), "+f"(c[1]), "+f"(c[2]), "+f"(c[3])
                     : "r"(a[0]), "r"(a[1]), "r"(a[2]), "r"(a[3]), "r"(b0), "r"(b1));
}

// ---------------- 1) norm: xn bf16 + x fp16 (+ zero g_cnt) ----------------
__global__ __launch_bounds__(256) void norm_kernel(const float* __restrict__ x) {
    int row = blockIdx.x, t = threadIdx.x;
    if (t == 0) g_cnt[row] = 0;
    float4 v = ((const float4*)(x + (size_t)row * DM))[t];

    ((ushort4*)(g_xh + (size_t)row * DM))[t] = make_ushort4(
        __half_as_ushort(__float2half_rn(v.x)), __half_as_ushort(__float2half_rn(v.y)),
        __half_as_ushort(__float2half_rn(v.z)), __half_as_ushort(__float2half_rn(v.w)));

    float ss = v.x * v.x + v.y * v.y + v.z * v.z + v.w * v.w;
    __shared__ float red[8];
#pragma unroll
    for (int o = 16; o; o >>= 1) ss += __shfl_xor_sync(~0u, ss, o);
    if ((t & 31) == 0) red[t >> 5] = ss;
    __syncthreads();
    if (t < 8) {
        float s = red[t];
#pragma unroll
        for (int o = 4; o; o >>= 1) s += __shfl_xor_sync(0xffu, s, o);
        if (t == 0) red[0] = s;
    }
    __syncthreads();
    float inv = 1.0f / fmaxf(sqrtf(red[0]), 1e-12f);
    ((ushort4*)(g_xnhi + (size_t)row * DM))[t] = make_ushort4(
        __bfloat16_as_ushort(__float2bfloat16_rn(v.x * inv)),
        __bfloat16_as_ushort(__float2bfloat16_rn(v.y * inv)),
        __bfloat16_as_ushort(__float2bfloat16_rn(v.z * inv)),
        __bfloat16_as_ushort(__float2bfloat16_rn(v.w * inv)));
}

// ---------------- 1b) Wv -> fp16 ----------------
__global__ __launch_bounds__(256) void convw_kernel(const float* __restrict__ Wv) {
    size_t i = (size_t)blockIdx.x * 1024 + threadIdx.x * 4;
    float4 v = *(const float4*)(Wv + i);
    *(ushort4*)(g_wvh + i) = make_ushort4(
        __half_as_ushort(__float2half_rn(v.x)), __half_as_ushort(__float2half_rn(v.y)),
        __half_as_ushort(__float2half_rn(v.z)), __half_as_ushort(__float2half_rn(v.w)));
}

// ---------------- HMMA GEMM core: 128x128 CTA tile, BK=32, 3-stage pipeline -
// A, B are 16-bit [rows][K=1024], K-contiguous. C = A * B^T.
#define LDSR 40                     // padded smem row: 40 elems = 80 B
#define SBUF (128 * LDSR)           // one stage: 5120 elems
#define STAGES 3
#define GEMM_SMEM (STAGES * SBUF * 2 * 2)   // 61440 B

__device__ __forceinline__ void g_load(const uint16_t* const* Aps,
                                       const uint16_t* const* Bps,
                                       uint32_t sA, uint32_t sB, int kt, int stage) {
    const int p = kt >> 5, kk = (kt & 31) * 32;
    const uint16_t* Ag = Aps[p] + kk;
    const uint16_t* Bg = Bps[p] + kk;
#pragma unroll
    for (int h = 0; h < 2; h++) {
        int id = threadIdx.x + h * 256;     // 0..511
        int row = id >> 2, c8 = (id & 3) * 8;
        uint32_t so = (uint32_t)(stage * SBUF + row * LDSR + c8) * 2;
        CP_ASYNC16(sA + so, Ag + (size_t)row * DM + c8);
        CP_ASYNC16(sB + so, Bg + (size_t)row * DM + c8);
    }
}

template <bool F16>
__device__ __forceinline__ void g_compute(uint32_t sA, uint32_t sB, int stage,
                                          int wm, int wn, int lane,
                                          float acc[4][4][4]) {
#pragma unroll
    for (int ks = 0; ks < 2; ks++) {
        const int col = ks * 16 + (lane >> 4) * 8;
        uint32_t af[4][4], bf[2][4];
#pragma unroll
        for (int mt = 0; mt < 4; mt++) {
            int row = wm * 64 + mt * 16 + (lane & 15);
            ldsm4(af[mt], sA + (uint32_t)(stage * SBUF + row * LDSR + col) * 2);
        }
#pragma unroll
        for (int nt2 = 0; nt2 < 2; nt2++) {
            int row = wn * 32 + nt2 * 16 + (lane & 15);
            ldsm4(bf[nt2], sB + (uint32_t)(stage * SBUF + row * LDSR + col) * 2);
        }
#pragma unroll
        for (int mt = 0; mt < 4; mt++)
#pragma unroll
            for (int nt = 0; nt < 4; nt++) {
                uint32_t b0 = (nt & 1) ? bf[nt >> 1][1] : bf[nt >> 1][0];
                uint32_t b1 = (nt & 1) ? bf[nt >> 1][3] : bf[nt >> 1][2];
                mma16816<F16>(acc[mt][nt], af[mt], b0, b1);
            }
    }
}

template <bool F16>
__device__ __forceinline__ void g_mainloop(const uint16_t* const* Aps,
                                           const uint16_t* const* Bps,
                                           int npass, char* dyn,
                                           float acc[4][4][4]) {
    const uint32_t sA = smem_u32(dyn);
    const uint32_t sB = sA + STAGES * SBUF * 2;
    const int lane = threadIdx.x & 31, wid = threadIdx.x >> 5;
    const int wm = wid & 1, wn = wid >> 1;
#pragma unroll
    for (int mt = 0; mt < 4; mt++)
#pragma unroll
        for (int nt = 0; nt < 4; nt++)
#pragma unroll
            for (int r = 0; r < 4; r++) acc[mt][nt][r] = 0.f;

    const int KT = npass * 32;
    g_load(Aps, Bps, sA, sB, 0, 0); CP_COMMIT();
    g_load(Aps, Bps, sA, sB, 1, 1); CP_COMMIT();
    int st = 0, stp = 2;                      // compute stage, prefetch stage
    for (int kt = 0; kt < KT; kt++) {
        if (kt + 1 < KT) CP_WAIT1(); else CP_WAIT0();
        __syncthreads();
        g_compute<F16>(sA, sB, st, wm, wn, lane, acc);
        if (kt + 2 < KT) {
            g_load(Aps, Bps, sA, sB, kt + 2, stp);
            CP_COMMIT();
        }
        if (++st == STAGES) st = 0;
        if (++stp == STAGES) stp = 0;
    }
}

// ---------------- 2) sim (upper-triangle tiles) -> compact idx lists --------
__global__ __launch_bounds__(256, 2) void sim_kernel() {
    extern __shared__ char dyn[];
    const int bz = blockIdx.y;
    int t = blockIdx.x, ti = 0;
    while (t >= 16 - ti) { t -= 16 - ti; ti++; }
    const int tj = ti + t;
    const int m0 = ti * 128, n0 = tj * 128;
    const bool diag = (ti == tj);

    const uint16_t* A = (const uint16_t*)(g_xnhi + ((size_t)bz * SEQ + m0) * DM);
    const uint16_t* B = (const uint16_t*)(g_xnhi + ((size_t)bz * SEQ + n0) * DM);
    const uint16_t* Aps[1] = {A};
    const uint16_t* Bps[1] = {B};
    float acc[4][4][4];
    g_mainloop<false>(Aps, Bps, 1, dyn, acc);
    __syncthreads();                          // smem reuse barrier

    unsigned char* T  = (unsigned char*)dyn;          // [128][132]
    unsigned char* TT = T + 128 * 132;                // transposed copy
    const int lane = threadIdx.x & 31, wid = threadIdx.x >> 5;
    const int wm = wid & 1, wn = wid >> 1;
#pragma unroll
    for (int mt = 0; mt < 4; mt++)
#pragma unroll
        for (int nt = 0; nt < 4; nt++)
#pragma unroll
            for (int rh = 0; rh < 2; rh++)
#pragma unroll
                for (int e = 0; e < 2; e++) {
                    int row = wm * 64 + mt * 16 + rh * 8 + (lane >> 2);
                    int col = wn * 32 + nt * 8 + (lane & 3) * 2 + e;
                    unsigned char bit = acc[mt][nt][rh * 2 + e] > 0.7f ? 1 : 0;
                    T[row * 132 + col] = bit;
                    if (!diag) TT[col * 132 + row] = bit;
                }
    __syncthreads();

    const int nview = diag ? 1 : 2;
    for (int vw = 0; vw < nview; vw++) {
        const unsigned char* M = vw ? TT : T;
        const int r0 = vw ? n0 : m0;          // global row base
        const int c0 = vw ? m0 : n0;          // global col base
#pragma unroll 2
        for (int r = 0; r < 16; r++) {
            int row = wid * 16 + r;
            unsigned m4 = *(const unsigned*)(M + row * 132 + lane * 4);
            int grow = bz * SEQ + r0 + row;
            int total = 0;
            unsigned bal[4];
            int pos[4];
#pragma unroll
            for (int sub = 0; sub < 4; sub++) {
                bool pred = ((m4 >> (8 * sub)) & 0xffu) != 0u;
                bal[sub] = __ballot_sync(~0u, pred);
                pos[sub] = total + __popc(bal[sub] & ((1u << lane) - 1u));
                total += __popc(bal[sub]);
            }
            if (total > 0) {
                int base = 0;
                if (lane == 0) base = atomicAdd(&g_cnt[grow], total);
                base = __shfl_sync(~0u, base, 0);
                unsigned short* lst = g_idx + (size_t)grow * SEQ + base;
#pragma unroll
                for (int sub = 0; sub < 4; sub++)
                    if ((bal[sub] >> lane) & 1u)
                        lst[pos[sub]] = (unsigned short)(c0 + lane * 4 + sub);
            }
        }
    }
}

// ---------------- 3) V projection: single-pass fp16 + bias ------------------
__global__ __launch_bounds__(256, 2) void proj_kernel(const float* __restrict__ bv) {
    extern __shared__ char dyn[];
    const int m0 = blockIdx.y * 128, n0 = blockIdx.x * 128;

    const uint16_t* Aps[1] = {(const uint16_t*)(g_xh + (size_t)m0 * DM)};
    const uint16_t* Bps[1] = {(const uint16_t*)(g_wvh + (size_t)n0 * DM)};
    float acc[4][4][4];
    g_mainloop<true>(Aps, Bps, 1, dyn, acc);

    const int lane = threadIdx.x & 31, wid = threadIdx.x >> 5;
    const int wm = wid & 1, wn = wid >> 1;
    const int mb = m0 + wm * 64 + (lane >> 2);
    const int nb = n0 + wn * 32 + (lane & 3) * 2;
    float2 bv2[4];
#pragma unroll
    for (int nt = 0; nt < 4; nt++)
        bv2[nt] = make_float2(__ldg(bv + nb + nt * 8), __ldg(bv + nb + nt * 8 + 1));
#pragma unroll
    for (int mt = 0; mt < 4; mt++)
#pragma unroll
        for (int rh = 0; rh < 2; rh++) {
            float* yr = g_v + (size_t)(mb + mt * 16 + rh * 8) * DM;
#pragma unroll
            for (int nt = 0; nt < 4; nt++) {
                float2 o = make_float2(acc[mt][nt][rh * 2 + 0] + bv2[nt].x,
                                       acc[mt][nt][rh * 2 + 1] + bv2[nt].y);
                *(float2*)(yr + nb + nt * 8) = o;
            }
        }
}

// ---------------- helper: on-the-fly fp32 projection of one head row --------
__device__ __forceinline__ void proj_row_head(const float* __restrict__ xr,
                                              const float* __restrict__ W,
                                              const float* __restrict__ bias,
                                              int h, int lane,
                                              float& r0, float& r1) {
    const float* w0 = W + (size_t)(h * DK + lane) * DM;
    const float* w1 = W + (size_t)(h * DK + lane + 32) * DM;
    r0 = bias[h * DK + lane];
    r1 = bias[h * DK + lane + 32];
    for (int k0 = 0; k0 < DM; k0 += 32) {
        float xv = xr[k0 + lane];
#pragma unroll
        for (int j = 0; j < 32; j++) {
            float xj = __shfl_sync(~0u, xv, j);
            r0 = fmaf(w0[k0 + j], xj, r0);
            r1 = fmaf(w1[k0 + j], xj, r1);
        }
    }
}

// ---------------- 4) sparse masked attention --------------------------------
__global__ __launch_bounds__(256) void attn_sparse_kernel(
        const float* __restrict__ x,
        const float* __restrict__ Wq, const float* __restrict__ bq,
        const float* __restrict__ Wk, const float* __restrict__ bk,
        float* __restrict__ out) {
    const int w = threadIdx.x >> 5, lane = threadIdx.x & 31;
    const int gw = blockIdx.x * 8 + w;
    const int h = gw & (NH - 1);
    const int row = gw >> 4;
    const int b = row >> 11, s = row & (SEQ - 1);

    const int cnt = g_cnt[row];
    const unsigned short* lst = g_idx + (size_t)row * SEQ;
    float* ob = out + (((size_t)b * NH + h) * SEQ + s) * DK;
    const float* Vb = g_v + (size_t)b * SEQ * DM + h * DK;

    if (cnt == 1) {
        const float* vp = Vb + (size_t)lst[0] * DM;
        ob[lane]      = vp[lane];
        ob[lane + 32] = vp[lane + 32];
        return;
    }

    // slow path: fp32 on-the-fly q/k
    const float* xb = x + (size_t)b * SEQ * DM;
    float q0, q1;
    proj_row_head(xb + (size_t)s * DM, Wq, bq, h, lane, q0, q1);

    float m = -1e30f, l = 0.f, o0 = 0.f, o1 = 0.f;
    for (int ci = 0; ci < cnt; ci++) {
        int tj = (int)lst[ci];
        float k0, k1;
        proj_row_head(xb + (size_t)tj * DM, Wk, bk, h, lane, k0, k1);
        float part = q0 * k0 + q1 * k1;
#pragma unroll
        for (int o = 16; o; o >>= 1) part += __shfl_xor_sync(~0u, part, o);
        float sc = part * 0.125f;             // 1/sqrt(64)
        float mn = fmaxf(m, sc);
        float alpha = __expf(m - mn);
        float p = __expf(sc - mn);
        l = l * alpha + p;
        const float* vp = Vb + (size_t)tj * DM;
        o0 = o0 * alpha + p * vp[lane];
        o1 = o1 * alpha + p * vp[lane + 32];
        m = mn;
    }
    float invl = 1.0f / l;
    ob[lane]      = o0 * invl;
    ob[lane + 32] = o1 * invl;
}

// ---------------- launch ----------------------------------------------------
extern "C" void kernel_launch(void* const* d_in, const int* in_sizes, int n_in,
                              void* d_out, int out_size) {
    const float* x  = (const float*)d_in[0];
    const float* Wq = (const float*)d_in[1];
    const float* bq = (const float*)d_in[2];
    const float* Wk = (const float*)d_in[3];
    const float* bk = (const float*)d_in[4];
    const float* Wv = (const float*)d_in[5];
    const float* bv = (const float*)d_in[6];
    float* out = (float*)d_out;

    cudaFuncSetAttribute(sim_kernel, cudaFuncAttributeMaxDynamicSharedMemorySize, GEMM_SMEM);
    cudaFuncSetAttribute(proj_kernel, cudaFuncAttributeMaxDynamicSharedMemorySize, GEMM_SMEM);

    norm_kernel<<<BATCH * SEQ, 256>>>(x);
    convw_kernel<<<DM * DM / 1024, 256>>>(Wv);
    sim_kernel<<<dim3(136, BATCH), 256, GEMM_SMEM>>>();
    proj_kernel<<<dim3(DM / 128, (BATCH * SEQ) / 128), 256, GEMM_SMEM>>>(bv);
    attn_sparse_kernel<<<(BATCH * SEQ * NH) / 8, 256>>>(x, Wq, bq, Wk, bk, out);
}

// round 10
// speedup vs baseline: 22.3039x; 1.0430x over previous
#include <cuda_runtime.h>
#include <cuda_bf16.h>
#include <cuda_fp16.h>
#include <cstdint>

#define BATCH 2
#define SEQ   2048
#define DM    1024
#define NH    16
#define DK    64

// ---------------- scratch (allocation-free: device globals) ----------------
__device__ __nv_bfloat16 g_xnhi[BATCH * SEQ * DM];   // normalized x, bf16 (sim)
__device__ __half g_xh[BATCH * SEQ * DM];            // x fp16 (V proj)
__device__ __half g_wvh[DM * DM];                    // Wv fp16
__device__ float g_v[BATCH * SEQ * DM];
__device__ unsigned short g_idx[(size_t)BATCH * SEQ * SEQ];
__device__ int g_cnt[BATCH * SEQ];

// ---------------- PTX helpers (sm_80-class: valid at base sm_103 target) ----
__device__ __forceinline__ uint32_t smem_u32(const void* p) {
    uint32_t a;
    asm("{ .reg .u64 t; cvta.to.shared.u64 t, %1; cvt.u32.u64 %0, t; }" : "=r"(a) : "l"(p));
    return a;
}
#define CP_ASYNC16(dst, src) \
    asm volatile("cp.async.cg.shared.global [%0], [%1], 16;" :: "r"(dst), "l"(src))
#define CP_COMMIT() asm volatile("cp.async.commit_group;" ::: "memory")
#define CP_WAIT2()  asm volatile("cp.async.wait_group 2;" ::: "memory")
#define CP_WAIT1()  asm volatile("cp.async.wait_group 1;" ::: "memory")
#define CP_WAIT0()  asm volatile("cp.async.wait_group 0;" ::: "memory")

__device__ __forceinline__ void ldsm4(uint32_t* r, uint32_t addr) {
    asm volatile("ldmatrix.sync.aligned.m8n8.x4.shared.b16 {%0,%1,%2,%3}, [%4];"
                 : "=r"(r[0]), "=r"(r[1]), "=r"(r[2]), "=r"(r[3]) : "r"(addr));
}
template <bool F16>
__device__ __forceinline__ void mma16816(float* c, const uint32_t* a, uint32_t b0, uint32_t b1) {
    if (F16)
        asm volatile("mma.sync.aligned.m16n8k16.row.col.f32.f16.f16.f32 "
                     "{%0,%1,%2,%3}, {%4,%5,%6,%7}, {%8,%9}, {%0,%1,%2,%3};"
                     : "+f"(c[0]), "+f"(c[1]), "+f"(c[2]), "+f"(c[3])
                     : "r"(a[0]), "r"(a[1]), "r"(a[2]), "r"(a[3]), "r"(b0), "r"(b1));
    else
        asm volatile("mma.sync.aligned.m16n8k16.row.col.f32.bf16.bf16.f32 "
                     "{%0,%1,%2,%3}, {%4,%5,%6,%7}, {%8,%9}, {%0,%1,%2,%3};"
                     : "+f"(c[0]), "+f"(c[1]), "+f"(c[2]), "+f"(c[3])
                     : "r"(a[0]), "r"(a[1]), "r"(a[2]), "r"(a[3]), "r"(b0), "r"(b1));
}

// ---------------- 1) prep: norm (+zero cnt) and Wv->fp16, fused -------------
__global__ __launch_bounds__(256) void prep_kernel(const float* __restrict__ x,
                                                   const float* __restrict__ Wv) {
    const int t = threadIdx.x;
    if (blockIdx.x >= BATCH * SEQ) {          // convw part: 1024 blocks
        size_t i = (size_t)(blockIdx.x - BATCH * SEQ) * 1024 + t * 4;
        float4 v = *(const float4*)(Wv + i);
        *(ushort4*)(g_wvh + i) = make_ushort4(
            __half_as_ushort(__float2half_rn(v.x)), __half_as_ushort(__float2half_rn(v.y)),
            __half_as_ushort(__float2half_rn(v.z)), __half_as_ushort(__float2half_rn(v.w)));
        return;
    }
    int row = blockIdx.x;
    if (t == 0) g_cnt[row] = 0;
    float4 v = ((const float4*)(x + (size_t)row * DM))[t];

    ((ushort4*)(g_xh + (size_t)row * DM))[t] = make_ushort4(
        __half_as_ushort(__float2half_rn(v.x)), __half_as_ushort(__float2half_rn(v.y)),
        __half_as_ushort(__float2half_rn(v.z)), __half_as_ushort(__float2half_rn(v.w)));

    float ss = v.x * v.x + v.y * v.y + v.z * v.z + v.w * v.w;
    __shared__ float red[8];
#pragma unroll
    for (int o = 16; o; o >>= 1) ss += __shfl_xor_sync(~0u, ss, o);
    if ((t & 31) == 0) red[t >> 5] = ss;
    __syncthreads();
    if (t < 8) {
        float s = red[t];
#pragma unroll
        for (int o = 4; o; o >>= 1) s += __shfl_xor_sync(0xffu, s, o);
        if (t == 0) red[0] = s;
    }
    __syncthreads();
    float inv = 1.0f / fmaxf(sqrtf(red[0]), 1e-12f);
    ((ushort4*)(g_xnhi + (size_t)row * DM))[t] = make_ushort4(
        __bfloat16_as_ushort(__float2bfloat16_rn(v.x * inv)),
        __bfloat16_as_ushort(__float2bfloat16_rn(v.y * inv)),
        __bfloat16_as_ushort(__float2bfloat16_rn(v.z * inv)),
        __bfloat16_as_ushort(__float2bfloat16_rn(v.w * inv)));
}

// ---------------- HMMA GEMM core: 128x128 CTA tile, BK=32, 4-stage depth-3 --
#define LDSR 40                     // padded smem row: 40 elems = 80 B
#define SBUF (128 * LDSR)           // one stage: 5120 elems
#define STAGES 4
#define GEMM_SMEM (STAGES * SBUF * 2 * 2)   // 81920 B

__device__ __forceinline__ void g_load(const uint16_t* const* Aps,
                                       const uint16_t* const* Bps,
                                       uint32_t sA, uint32_t sB, int kt, int stage) {
    const int p = kt >> 5, kk = (kt & 31) * 32;
    const uint16_t* Ag = Aps[p] + kk;
    const uint16_t* Bg = Bps[p] + kk;
#pragma unroll
    for (int h = 0; h < 2; h++) {
        int id = threadIdx.x + h * 256;     // 0..511
        int row = id >> 2, c8 = (id & 3) * 8;
        uint32_t so = (uint32_t)(stage * SBUF + row * LDSR + c8) * 2;
        CP_ASYNC16(sA + so, Ag + (size_t)row * DM + c8);
        CP_ASYNC16(sB + so, Bg + (size_t)row * DM + c8);
    }
}

template <bool F16>
__device__ __forceinline__ void g_compute(uint32_t sA, uint32_t sB, int stage,
                                          int wm, int wn, int lane,
                                          float acc[4][4][4]) {
#pragma unroll
    for (int ks = 0; ks < 2; ks++) {
        const int col = ks * 16 + (lane >> 4) * 8;
        uint32_t af[4][4], bf[2][4];
#pragma unroll
        for (int mt = 0; mt < 4; mt++) {
            int row = wm * 64 + mt * 16 + (lane & 15);
            ldsm4(af[mt], sA + (uint32_t)(stage * SBUF + row * LDSR + col) * 2);
        }
#pragma unroll
        for (int nt2 = 0; nt2 < 2; nt2++) {
            int row = wn * 32 + nt2 * 16 + (lane & 15);
            ldsm4(bf[nt2], sB + (uint32_t)(stage * SBUF + row * LDSR + col) * 2);
        }
#pragma unroll
        for (int mt = 0; mt < 4; mt++)
#pragma unroll
            for (int nt = 0; nt < 4; nt++) {
                uint32_t b0 = (nt & 1) ? bf[nt >> 1][1] : bf[nt >> 1][0];
                uint32_t b1 = (nt & 1) ? bf[nt >> 1][3] : bf[nt >> 1][2];
                mma16816<F16>(acc[mt][nt], af[mt], b0, b1);
            }
    }
}

template <bool F16>
__device__ __forceinline__ void g_mainloop(const uint16_t* const* Aps,
                                           const uint16_t* const* Bps,
                                           int npass, char* dyn,
                                           float acc[4][4][4]) {
    const uint32_t sA = smem_u32(dyn);
    const uint32_t sB = sA + STAGES * SBUF * 2;
    const int lane = threadIdx.x & 31, wid = threadIdx.x >> 5;
    const int wm = wid & 1, wn = wid >> 1;
#pragma unroll
    for (int mt = 0; mt < 4; mt++)
#pragma unroll
        for (int nt = 0; nt < 4; nt++)
#pragma unroll
            for (int r = 0; r < 4; r++) acc[mt][nt][r] = 0.f;

    const int KT = npass * 32;                // >= 16
    g_load(Aps, Bps, sA, sB, 0, 0); CP_COMMIT();
    g_load(Aps, Bps, sA, sB, 1, 1); CP_COMMIT();
    g_load(Aps, Bps, sA, sB, 2, 2); CP_COMMIT();
    for (int kt = 0; kt < KT; kt++) {
        if (kt < KT - 2) CP_WAIT2();
        else if (kt == KT - 2) CP_WAIT1();
        else CP_WAIT0();
        __syncthreads();
        // stage being computed: kt%4. Stage loaded below: (kt+3)%4 == (kt-1)%4,
        // whose compute finished before the barrier above -> safe.
        g_compute<F16>(sA, sB, kt & 3, wm, wn, lane, acc);
        if (kt + 3 < KT) {
            g_load(Aps, Bps, sA, sB, kt + 3, (kt + 3) & 3);
            CP_COMMIT();
        }
    }
}

// ---------------- 2+3) fused GEMM kernel: proj blocks then sim blocks -------
// grid.x = 256 (proj) + 272 (sim upper-triangle tile-pairs)
__global__ __launch_bounds__(256, 2) void gemm_kernel(const float* __restrict__ bv) {
    extern __shared__ char dyn[];
    const int lane = threadIdx.x & 31, wid = threadIdx.x >> 5;
    const int wm = wid & 1, wn = wid >> 1;

    if (blockIdx.x < 256) {
        // ---- V projection: single-pass fp16 + bias ----
        const int m0 = (blockIdx.x >> 3) * 128, n0 = (blockIdx.x & 7) * 128;
        const uint16_t* Aps[1] = {(const uint16_t*)(g_xh + (size_t)m0 * DM)};
        const uint16_t* Bps[1] = {(const uint16_t*)(g_wvh + (size_t)n0 * DM)};
        float acc[4][4][4];
        g_mainloop<true>(Aps, Bps, 1, dyn, acc);

        const int mb = m0 + wm * 64 + (lane >> 2);
        const int nb = n0 + wn * 32 + (lane & 3) * 2;
        float2 bv2[4];
#pragma unroll
        for (int nt = 0; nt < 4; nt++)
            bv2[nt] = make_float2(__ldg(bv + nb + nt * 8), __ldg(bv + nb + nt * 8 + 1));
#pragma unroll
        for (int mt = 0; mt < 4; mt++)
#pragma unroll
            for (int rh = 0; rh < 2; rh++) {
                float* yr = g_v + (size_t)(mb + mt * 16 + rh * 8) * DM;
#pragma unroll
                for (int nt = 0; nt < 4; nt++) {
                    float2 o = make_float2(acc[mt][nt][rh * 2 + 0] + bv2[nt].x,
                                           acc[mt][nt][rh * 2 + 1] + bv2[nt].y);
                    *(float2*)(yr + nb + nt * 8) = o;
                }
            }
        return;
    }

    // ---- sim tile-pair -> threshold -> compact idx lists ----
    const int idx = blockIdx.x - 256;
    const int bz = idx / 136;
    int t = idx % 136, ti = 0;
    while (t >= 16 - ti) { t -= 16 - ti; ti++; }
    const int tj = ti + t;
    const int m0 = ti * 128, n0 = tj * 128;
    const bool diag = (ti == tj);

    const uint16_t* A = (const uint16_t*)(g_xnhi + ((size_t)bz * SEQ + m0) * DM);
    const uint16_t* B = (const uint16_t*)(g_xnhi + ((size_t)bz * SEQ + n0) * DM);
    const uint16_t* Aps[1] = {A};
    const uint16_t* Bps[1] = {B};
    float acc[4][4][4];
    g_mainloop<false>(Aps, Bps, 1, dyn, acc);   // KT=32? no: npass=1 -> 32 iters of K... (K=1024 => 32 iters)
    __syncthreads();                            // smem reuse barrier

    unsigned char* T  = (unsigned char*)dyn;    // [128][132]
    unsigned char* TT = T + 128 * 132;          // transposed copy
#pragma unroll
    for (int mt = 0; mt < 4; mt++)
#pragma unroll
        for (int nt = 0; nt < 4; nt++)
#pragma unroll
            for (int rh = 0; rh < 2; rh++)
#pragma unroll
                for (int e = 0; e < 2; e++) {
                    int row = wm * 64 + mt * 16 + rh * 8 + (lane >> 2);
                    int col = wn * 32 + nt * 8 + (lane & 3) * 2 + e;
                    unsigned char bit = acc[mt][nt][rh * 2 + e] > 0.7f ? 1 : 0;
                    T[row * 132 + col] = bit;
                    if (!diag) TT[col * 132 + row] = bit;
                }
    __syncthreads();

    const int nview = diag ? 1 : 2;
    for (int vw = 0; vw < nview; vw++) {
        const unsigned char* M = vw ? TT : T;
        const int r0 = vw ? n0 : m0;            // global row base
        const int c0 = vw ? m0 : n0;            // global col base
#pragma unroll 2
        for (int r = 0; r < 16; r++) {
            int row = wid * 16 + r;
            unsigned m4 = *(const unsigned*)(M + row * 132 + lane * 4);
            int grow = bz * SEQ + r0 + row;
            int total = 0;
            unsigned bal[4];
            int pos[4];
#pragma unroll
            for (int sub = 0; sub < 4; sub++) {
                bool pred = ((m4 >> (8 * sub)) & 0xffu) != 0u;
                bal[sub] = __ballot_sync(~0u, pred);
                pos[sub] = total + __popc(bal[sub] & ((1u << lane) - 1u));
                total += __popc(bal[sub]);
            }
            if (total > 0) {
                int base = 0;
                if (lane == 0) base = atomicAdd(&g_cnt[grow], total);
                base = __shfl_sync(~0u, base, 0);
                unsigned short* lst = g_idx + (size_t)grow * SEQ + base;
#pragma unroll
                for (int sub = 0; sub < 4; sub++)
                    if ((bal[sub] >> lane) & 1u)
                        lst[pos[sub]] = (unsigned short)(c0 + lane * 4 + sub);
            }
        }
    }
}

// ---------------- helper: on-the-fly fp32 projection of one head row --------
__device__ __forceinline__ void proj_row_head(const float* __restrict__ xr,
                                              const float* __restrict__ W,
                                              const float* __restrict__ bias,
                                              int h, int lane,
                                              float& r0, float& r1) {
    const float* w0 = W + (size_t)(h * DK + lane) * DM;
    const float* w1 = W + (size_t)(h * DK + lane + 32) * DM;
    r0 = bias[h * DK + lane];
    r1 = bias[h * DK + lane + 32];
    for (int k0 = 0; k0 < DM; k0 += 32) {
        float xv = xr[k0 + lane];
#pragma unroll
        for (int j = 0; j < 32; j++) {
            float xj = __shfl_sync(~0u, xv, j);
            r0 = fmaf(w0[k0 + j], xj, r0);
            r1 = fmaf(w1[k0 + j], xj, r1);
        }
    }
}

// ---------------- 4) sparse masked attention --------------------------------
__global__ __launch_bounds__(256) void attn_sparse_kernel(
        const float* __restrict__ x,
        const float* __restrict__ Wq, const float* __restrict__ bq,
        const float* __restrict__ Wk, const float* __restrict__ bk,
        float* __restrict__ out) {
    const int w = threadIdx.x >> 5, lane = threadIdx.x & 31;
    const int gw = blockIdx.x * 8 + w;
    const int h = gw & (NH - 1);
    const int row = gw >> 4;
    const int b = row >> 11, s = row & (SEQ - 1);

    const int cnt = g_cnt[row];
    const unsigned short* lst = g_idx + (size_t)row * SEQ;
    float* ob = out + (((size_t)b * NH + h) * SEQ + s) * DK;
    const float* Vb = g_v + (size_t)b * SEQ * DM + h * DK;

    if (cnt == 1) {
        const float* vp = Vb + (size_t)lst[0] * DM;
        ob[lane]      = vp[lane];
        ob[lane + 32] = vp[lane + 32];
        return;
    }

    // slow path: fp32 on-the-fly q/k
    const float* xb = x + (size_t)b * SEQ * DM;
    float q0, q1;
    proj_row_head(xb + (size_t)s * DM, Wq, bq, h, lane, q0, q1);

    float m = -1e30f, l = 0.f, o0 = 0.f, o1 = 0.f;
    for (int ci = 0; ci < cnt; ci++) {
        int tj = (int)lst[ci];
        float k0, k1;
        proj_row_head(xb + (size_t)tj * DM, Wk, bk, h, lane, k0, k1);
        float part = q0 * k0 + q1 * k1;
#pragma unroll
        for (int o = 16; o; o >>= 1) part += __shfl_xor_sync(~0u, part, o);
        float sc = part * 0.125f;             // 1/sqrt(64)
        float mn = fmaxf(m, sc);
        float alpha = __expf(m - mn);
        float p = __expf(sc - mn);
        l = l * alpha + p;
        const float* vp = Vb + (size_t)tj * DM;
        o0 = o0 * alpha + p * vp[lane];
        o1 = o1 * alpha + p * vp[lane + 32];
        m = mn;
    }
    float invl = 1.0f / l;
    ob[lane]      = o0 * invl;
    ob[lane + 32] = o1 * invl;
}

// ---------------- launch ----------------------------------------------------
extern "C" void kernel_launch(void* const* d_in, const int* in_sizes, int n_in,
                              void* d_out, int out_size) {
    const float* x  = (const float*)d_in[0];
    const float* Wq = (const float*)d_in[1];
    const float* bq = (const float*)d_in[2];
    const float* Wk = (const float*)d_in[3];
    const float* bk = (const float*)d_in[4];
    const float* Wv = (const float*)d_in[5];
    const float* bv = (const float*)d_in[6];
    float* out = (float*)d_out;

    cudaFuncSetAttribute(gemm_kernel, cudaFuncAttributeMaxDynamicSharedMemorySize, GEMM_SMEM);

    prep_kernel<<<BATCH * SEQ + DM * DM / 1024, 256>>>(x, Wv);
    gemm_kernel<<<256 + 136 * BATCH, 256, GEMM_SMEM>>>(bv);
    attn_sparse_kernel<<<(BATCH * SEQ * NH) / 8, 256>>>(x, Wq, bq, Wk, bk, out);
}